// round 5
// baseline (speedup 1.0000x reference)
#include <cuda_runtime.h>
#include <math.h>

// Problem constants
#define Bq      4
#define C       192
#define C3      576       // 3*C (qkv channels)
#define HEADS   8
#define HD      24        // head dim
#define HIDDEN  510
#define FF2     1020      // 2*HIDDEN
#define Hh      128
#define Wd      128
#define HW      16384
#define EPS_LN  1e-5f

// ---------------------------------------------------------------------------
// Static scratch (allocation-free rule: __device__ globals)
// ---------------------------------------------------------------------------
__device__ float g_ln  [(size_t)Bq * C   * HW];   // layernorm output (both uses)
__device__ float g_t1  [(size_t)Bq * FF2 * HW];   // qkv pre-dw / ffn pre-dw / gated
__device__ float g_t2  [(size_t)Bq * FF2 * HW];   // qkv post-dw / ffn post-dw
__device__ float g_xmid[(size_t)Bq * C   * HW];   // x + attention(...)
__device__ float g_wm  [Bq * C * C];              // fused W_proj @ blockdiag(attn)
__device__ float g_attn[Bq * HEADS * HD * HD];    // raw gram -> softmax probs
__device__ float g_invq[Bq * C];
__device__ float g_invk[Bq * C];

// ---------------------------------------------------------------------------
// LayerNorm over channel dim (per pixel), NCHW
// ---------------------------------------------------------------------------
__global__ void ln_kernel(const float* __restrict__ x, const float* __restrict__ w,
                          const float* __restrict__ bias, float* __restrict__ out)
{
    int idx = blockIdx.x * blockDim.x + threadIdx.x;
    if (idx >= Bq * HW) return;
    int b = idx >> 14;
    int pix = idx & (HW - 1);
    const float* xp = x + (size_t)b * C * HW + pix;
    float s = 0.f, s2 = 0.f;
    #pragma unroll 8
    for (int c = 0; c < C; c++) {
        float v = xp[(size_t)c * HW];
        s += v; s2 += v * v;
    }
    float mu  = s * (1.f / C);
    float var = s2 * (1.f / C) - mu * mu;
    float r   = rsqrtf(var + EPS_LN);
    float* op = out + (size_t)b * C * HW + pix;
    #pragma unroll 8
    for (int c = 0; c < C; c++)
        op[(size_t)c * HW] = (xp[(size_t)c * HW] - mu) * r * w[c] + bias[c];
}

// ---------------------------------------------------------------------------
// SGEMM: C[b] (MxN) = W[b] (MxK) @ X[b] (KxN) (+ Res[b])
// Tiles: BM=64, BN=128, BK=8; 256 threads; 4x8 register tile per thread.
// Per-batch strides passed explicitly (elements).
// ---------------------------------------------------------------------------
__global__ void __launch_bounds__(256)
sgemm_kernel(const float* __restrict__ Wt, const float* __restrict__ X,
             float* __restrict__ Cm, const float* __restrict__ Res,
             int M, int N, int K,
             long wB, long xB, long cB)
{
    const int b = blockIdx.z;
    const float* Wb = Wt + (size_t)b * wB;
    const float* Xb = X  + (size_t)b * xB;
    float*       Cb = Cm + (size_t)b * cB;
    const float* Rb = Res ? (Res + (size_t)b * cB) : nullptr;

    __shared__ float As[8][64];    // A transposed: As[k][m]
    __shared__ float Bs[8][128];

    const int tid = threadIdx.x;
    const int tx  = tid & 15;      // n group  (8 cols each)
    const int ty  = tid >> 4;      // m group  (4 rows each)
    const int m0  = blockIdx.y * 64;
    const int n0  = blockIdx.x * 128;

    float acc[4][8];
    #pragma unroll
    for (int i = 0; i < 4; i++)
        #pragma unroll
        for (int j = 0; j < 8; j++) acc[i][j] = 0.f;

    for (int k0 = 0; k0 < K; k0 += 8) {
        // A tile: 64x8
        #pragma unroll
        for (int i = tid; i < 512; i += 256) {
            int m = i >> 3, k = i & 7;
            float v = 0.f;
            if (m0 + m < M && k0 + k < K) v = Wb[(size_t)(m0 + m) * K + k0 + k];
            As[k][m] = v;
        }
        // B tile: 8x128 (coalesced)
        #pragma unroll
        for (int i = tid; i < 1024; i += 256) {
            int k = i >> 7, n = i & 127;
            float v = 0.f;
            if (k0 + k < K) v = Xb[(size_t)(k0 + k) * N + n0 + n];
            Bs[k][n] = v;
        }
        __syncthreads();
        #pragma unroll
        for (int k = 0; k < 8; k++) {
            float a[4], bb[8];
            #pragma unroll
            for (int i = 0; i < 4; i++) a[i] = As[k][ty * 4 + i];
            #pragma unroll
            for (int j = 0; j < 8; j++) bb[j] = Bs[k][tx * 8 + j];
            #pragma unroll
            for (int i = 0; i < 4; i++)
                #pragma unroll
                for (int j = 0; j < 8; j++) acc[i][j] += a[i] * bb[j];
        }
        __syncthreads();
    }

    #pragma unroll
    for (int i = 0; i < 4; i++) {
        int m = m0 + ty * 4 + i;
        if (m >= M) continue;
        size_t off = (size_t)m * N + n0 + tx * 8;
        #pragma unroll
        for (int j = 0; j < 8; j++) {
            float v = acc[i][j];
            if (Rb) v += Rb[off + j];
            Cb[off + j] = v;
        }
    }
}

// ---------------------------------------------------------------------------
// Depthwise 3x3 conv, SAME padding, NCHW; per-batch channel count Cch
// ---------------------------------------------------------------------------
__global__ void dwconv_kernel(const float* __restrict__ in, const float* __restrict__ w,
                              float* __restrict__ out, int Cch)
{
    size_t idx = (size_t)blockIdx.x * blockDim.x + threadIdx.x;
    size_t total = (size_t)Bq * Cch * HW;
    if (idx >= total) return;
    int pix = (int)(idx & (HW - 1));
    size_t bc = idx >> 14;
    int c = (int)(bc % Cch);
    int x = pix & (Wd - 1);
    int y = pix >> 7;
    const float* ip = in + (bc << 14);
    const float* wc = w + (size_t)c * 9;
    float s = 0.f;
    #pragma unroll
    for (int dy = -1; dy <= 1; dy++) {
        int yy = y + dy;
        if (yy < 0 || yy >= Hh) continue;
        #pragma unroll
        for (int dx = -1; dx <= 1; dx++) {
            int xx = x + dx;
            if (xx < 0 || xx >= Wd) continue;
            s += wc[(dy + 1) * 3 + (dx + 1)] * ip[yy * Wd + xx];
        }
    }
    out[idx] = s;
}

// ---------------------------------------------------------------------------
// 1/l2norm over hw for q (ch 0..191) and k (ch 192..383) rows of g_t2
// ---------------------------------------------------------------------------
__global__ void invnorm_kernel()
{
    int row = blockIdx.x;                 // 0 .. Bq*384-1
    int b = row / (2 * C), c = row % (2 * C);
    const float* p = g_t2 + ((size_t)b * C3 + c) * HW;
    float s = 0.f;
    for (int i = threadIdx.x; i < HW; i += 256) { float v = p[i]; s += v * v; }
    __shared__ float red[256];
    red[threadIdx.x] = s;
    __syncthreads();
    for (int st = 128; st > 0; st >>= 1) {
        if (threadIdx.x < st) red[threadIdx.x] += red[threadIdx.x + st];
        __syncthreads();
    }
    if (threadIdx.x == 0) {
        float inv = 1.f / fmaxf(sqrtf(red[0]), 1e-12f);
        if (c < C) g_invq[b * C + c] = inv;
        else       g_invk[b * C + c - C] = inv;
    }
}

__global__ void zero_attn_kernel()
{
    int i = blockIdx.x * blockDim.x + threadIdx.x;
    if (i < Bq * HEADS * HD * HD) g_attn[i] = 0.f;
}

// ---------------------------------------------------------------------------
// Gram matrices: attn_raw[b,h,d,c] = sum_p q[b,h,d,p] * k[b,h,c,p]
// grid (Bq*HEADS, 16 k-splits), 64 threads each computing a 3x3 output tile.
// ---------------------------------------------------------------------------
#define GSPLIT 16
#define GBK    128
__global__ void gram_kernel()
{
    int bh = blockIdx.x;                    // 0..31
    int split = blockIdx.y;                 // 0..15
    int b = bh >> 3, h = bh & 7;
    const float* qbase = g_t2 + ((size_t)b * C3 + h * HD) * HW;
    const float* kbase = g_t2 + ((size_t)b * C3 + C + h * HD) * HW;

    __shared__ float qs[HD][GBK + 4];
    __shared__ float ks[HD][GBK + 4];

    int tid = threadIdx.x;                  // 64
    int tx = tid & 7, ty = tid >> 3;        // 8x8 thread grid, 3x3 tiles
    float acc[3][3] = {{0.f}};

    int p0 = split * (HW / GSPLIT);
    for (int t = 0; t < (HW / GSPLIT) / GBK; t++) {   // 8 tiles
        int pb = p0 + t * GBK;
        for (int i = tid; i < 2 * HD * GBK; i += 64) {
            int r = i >> 7, k = i & (GBK - 1);
            if (r < HD) qs[r][k]      = qbase[(size_t)r * HW + pb + k];
            else        ks[r - HD][k] = kbase[(size_t)(r - HD) * HW + pb + k];
        }
        __syncthreads();
        #pragma unroll 4
        for (int k = 0; k < GBK; k++) {
            float qv[3], kv[3];
            #pragma unroll
            for (int ii = 0; ii < 3; ii++) qv[ii] = qs[ty * 3 + ii][k];
            #pragma unroll
            for (int jj = 0; jj < 3; jj++) kv[jj] = ks[tx * 3 + jj][k];
            #pragma unroll
            for (int ii = 0; ii < 3; ii++)
                #pragma unroll
                for (int jj = 0; jj < 3; jj++) acc[ii][jj] += qv[ii] * kv[jj];
        }
        __syncthreads();
    }
    float* dst = g_attn + (size_t)bh * HD * HD;
    #pragma unroll
    for (int ii = 0; ii < 3; ii++)
        #pragma unroll
        for (int jj = 0; jj < 3; jj++)
            atomicAdd(&dst[(ty * 3 + ii) * HD + tx * 3 + jj], acc[ii][jj]);
}

// ---------------------------------------------------------------------------
// Softmax per row with fused l2norm scaling + temperature
// ---------------------------------------------------------------------------
__global__ void softmax_kernel(const float* __restrict__ temp)
{
    int bh = blockIdx.x;
    int b = bh >> 3, h = bh & 7;
    int i = threadIdx.x;
    if (i >= HD) return;
    float* row = g_attn + (size_t)bh * HD * HD + i * HD;
    float qi = g_invq[b * C + h * HD + i] * temp[h];
    float vals[HD];
    float mx = -1e30f;
    #pragma unroll
    for (int j = 0; j < HD; j++) {
        float v = row[j] * qi * g_invk[b * C + h * HD + j];
        vals[j] = v;
        mx = fmaxf(mx, v);
    }
    float s = 0.f;
    #pragma unroll
    for (int j = 0; j < HD; j++) { vals[j] = expf(vals[j] - mx); s += vals[j]; }
    float inv = 1.f / s;
    #pragma unroll
    for (int j = 0; j < HD; j++) row[j] = vals[j] * inv;
}

// ---------------------------------------------------------------------------
// Fuse W_proj with block-diagonal attention:
// wm[b][o][h*HD+c] = sum_d W_proj[o][h*HD+d] * attn[b,h,d,c]
// ---------------------------------------------------------------------------
__global__ void wm_kernel(const float* __restrict__ wproj)
{
    int idx = blockIdx.x * 256 + threadIdx.x;
    if (idx >= Bq * C * C) return;
    int cc = idx % C;
    int o  = (idx / C) % C;
    int b  = idx / (C * C);
    int h = cc / HD, ci = cc % HD;
    const float* wrow = wproj + (size_t)o * C + h * HD;
    const float* arow = g_attn + ((size_t)(b * HEADS + h) * HD) * HD + ci;
    float s = 0.f;
    #pragma unroll
    for (int d = 0; d < HD; d++) s += wrow[d] * arow[d * HD];
    g_wm[idx] = s;
}

// ---------------------------------------------------------------------------
// GDFN gating: gelu(x1) * x2  (exact erf gelu)
// ---------------------------------------------------------------------------
__global__ void gated_kernel()
{
    size_t idx = (size_t)blockIdx.x * 256 + threadIdx.x;
    size_t total = (size_t)Bq * HIDDEN * HW;
    if (idx >= total) return;
    int pix = (int)(idx & (HW - 1));
    size_t bc = idx >> 14;
    int b = (int)(bc / HIDDEN);
    int j = (int)(bc % HIDDEN);
    const float* base = g_t2 + (size_t)b * FF2 * HW;
    float x1 = base[(size_t)j * HW + pix];
    float x2 = base[(size_t)(HIDDEN + j) * HW + pix];
    float g = 0.5f * x1 * (1.f + erff(x1 * 0.70710678118654752f));
    g_t1[((size_t)b * HIDDEN + j) * HW + pix] = g * x2;
}

// ---------------------------------------------------------------------------
// Launch sequence (graph-capturable: kernel launches only)
// ---------------------------------------------------------------------------
extern "C" void kernel_launch(void* const* d_in, const int* in_sizes, int n_in,
                              void* d_out, int out_size)
{
    const float* x      = (const float*)d_in[0];
    const float* temp   = (const float*)d_in[1];
    const float* ln1w   = (const float*)d_in[2];
    const float* ln1b   = (const float*)d_in[3];
    const float* ln2w   = (const float*)d_in[4];
    const float* ln2b   = (const float*)d_in[5];
    const float* w_qkv  = (const float*)d_in[6];
    const float* w_qkvd = (const float*)d_in[7];
    const float* w_proj = (const float*)d_in[8];
    const float* w_in   = (const float*)d_in[9];
    const float* w_dw   = (const float*)d_in[10];
    const float* w_out  = (const float*)d_in[11];
    float* out = (float*)d_out;

    float *p_ln, *p_t1, *p_t2, *p_xmid, *p_wm;
    cudaGetSymbolAddress((void**)&p_ln,   g_ln);
    cudaGetSymbolAddress((void**)&p_t1,   g_t1);
    cudaGetSymbolAddress((void**)&p_t2,   g_t2);
    cudaGetSymbolAddress((void**)&p_xmid, g_xmid);
    cudaGetSymbolAddress((void**)&p_wm,   g_wm);

    const long sC   = (long)C * HW;       // 192*16384
    const long sC3  = (long)C3 * HW;      // 576*16384
    const long sFF2 = (long)FF2 * HW;     // 1020*16384
    const long sHID = (long)HIDDEN * HW;  // 510*16384

    // 1. ln1(x) -> g_ln
    ln_kernel<<<(Bq * HW + 255) / 256, 256>>>(x, ln1w, ln1b, p_ln);

    // 2. qkv = W_qkv @ ln  (576 x 16384, K=192) -> g_t1
    sgemm_kernel<<<dim3(HW / 128, (C3 + 63) / 64, Bq), 256>>>(
        w_qkv, p_ln, p_t1, nullptr, C3, HW, C, 0, sC, sC3);

    // 3. depthwise 3x3 -> g_t2
    {
        size_t total = (size_t)Bq * C3 * HW;
        dwconv_kernel<<<(unsigned)((total + 255) / 256), 256>>>(p_t1, w_qkvd, p_t2, C3);
    }

    // 4. l2 inverse norms of q,k rows; zero attn accumulator
    invnorm_kernel<<<Bq * 2 * C, 256>>>();
    zero_attn_kernel<<<(Bq * HEADS * HD * HD + 255) / 256, 256>>>();

    // 5. q @ k^T gram matrices (split-K atomics)
    gram_kernel<<<dim3(Bq * HEADS, GSPLIT), 64>>>();

    // 6. softmax with fused normalization + temperature
    softmax_kernel<<<Bq * HEADS, 32>>>(temp);

    // 7. wm = W_proj @ blockdiag(attn)   (per batch 192x192)
    wm_kernel<<<(Bq * C * C + 255) / 256, 256>>>(w_proj);

    // 8. xmid = wm @ v + x    (v = g_t2 channels [384..576))
    sgemm_kernel<<<dim3(HW / 128, C / 64, Bq), 256>>>(
        p_wm, p_t2 + (size_t)2 * C * HW, p_xmid, x,
        C, HW, C, (long)C * C, sC3, sC);

    // 9. ln2(xmid) -> g_ln
    ln_kernel<<<(Bq * HW + 255) / 256, 256>>>(p_xmid, ln2w, ln2b, p_ln);

    // 10. ffn hidden = W_in @ ln  (1020 x 16384, K=192) -> g_t1
    sgemm_kernel<<<dim3(HW / 128, (FF2 + 63) / 64, Bq), 256>>>(
        w_in, p_ln, p_t1, nullptr, FF2, HW, C, 0, sC, sFF2);

    // 11. depthwise 3x3 -> g_t2
    {
        size_t total = (size_t)Bq * FF2 * HW;
        dwconv_kernel<<<(unsigned)((total + 255) / 256), 256>>>(p_t1, w_dw, p_t2, FF2);
    }

    // 12. gated = gelu(x1) * x2 -> g_t1 (510 ch per batch)
    {
        size_t total = (size_t)Bq * HIDDEN * HW;
        gated_kernel<<<(unsigned)((total + 255) / 256), 256>>>();
    }

    // 13. out = W_out @ gated + xmid  (192 x 16384, K=510)
    sgemm_kernel<<<dim3(HW / 128, C / 64, Bq), 256>>>(
        w_out, p_t1, out, p_xmid, C, HW, HIDDEN, 0, sHID, sC);
}

// round 6
// speedup vs baseline: 2.0400x; 2.0400x over previous
#include <cuda_runtime.h>
#include <math.h>

// Problem constants
#define Bq      4
#define C       192
#define C3      576       // 3*C (qkv channels)
#define HEADS   8
#define HD      24        // head dim
#define HIDDEN  510
#define FF2     1020      // 2*HIDDEN
#define Hh      128
#define Wd      128
#define HW      16384
#define EPS_LN  1e-5f

// ---------------------------------------------------------------------------
// Static scratch
// ---------------------------------------------------------------------------
__device__ float g_ln  [(size_t)Bq * C   * HW];
__device__ float g_t1  [(size_t)Bq * FF2 * HW];
__device__ float g_t2  [(size_t)Bq * FF2 * HW];
__device__ float g_xmid[(size_t)Bq * C   * HW];
__device__ float g_wm  [Bq * C * C];
__device__ float g_attn[Bq * HEADS * HD * HD];
__device__ float g_sq  [Bq * 2 * C];
__device__ float g_invq[Bq * C];
__device__ float g_invk[Bq * C];

// ---------------------------------------------------------------------------
// LayerNorm over channel dim (per pixel), NCHW
// ---------------------------------------------------------------------------
__global__ void ln_kernel(const float* __restrict__ x, const float* __restrict__ w,
                          const float* __restrict__ bias, float* __restrict__ out)
{
    int idx = blockIdx.x * blockDim.x + threadIdx.x;
    if (idx >= Bq * HW) return;
    int b = idx >> 14;
    int pix = idx & (HW - 1);
    const float* xp = x + (size_t)b * C * HW + pix;
    float s = 0.f, s2 = 0.f;
    #pragma unroll 8
    for (int c = 0; c < C; c++) {
        float v = xp[(size_t)c * HW];
        s += v; s2 += v * v;
    }
    float mu  = s * (1.f / C);
    float var = s2 * (1.f / C) - mu * mu;
    float r   = rsqrtf(var + EPS_LN);
    float* op = out + (size_t)b * C * HW + pix;
    #pragma unroll 8
    for (int c = 0; c < C; c++)
        op[(size_t)c * HW] = (xp[(size_t)c * HW] - mu) * r * w[c] + bias[c];
}

// ---------------------------------------------------------------------------
// TF32 tensor-core GEMM: C[b] (MxN) = W[b] (MxK) @ X[b] (KxN) (+ Res[b])
// BM=128 BN=128 BK=16, 256 threads (8 warps, warp tile 32x64),
// mma.sync.aligned.m16n8k8.row.col.f32.tf32.tf32.f32
// ---------------------------------------------------------------------------
#define BM 128
#define BN 128
#define BK 16

__device__ __forceinline__ unsigned f2tf(float f)
{
    unsigned u;
    asm("cvt.rna.tf32.f32 %0, %1;" : "=r"(u) : "f"(f));
    return u;
}

__device__ __forceinline__ void mma_tf32(float c[4], const unsigned a[4], const unsigned b[2])
{
    asm volatile(
        "mma.sync.aligned.m16n8k8.row.col.f32.tf32.tf32.f32 "
        "{%0,%1,%2,%3}, {%4,%5,%6,%7}, {%8,%9}, {%0,%1,%2,%3};"
        : "+f"(c[0]), "+f"(c[1]), "+f"(c[2]), "+f"(c[3])
        : "r"(a[0]), "r"(a[1]), "r"(a[2]), "r"(a[3]), "r"(b[0]), "r"(b[1]));
}

__global__ void __launch_bounds__(256, 2)
tf32_gemm_kernel(const float* __restrict__ Wt, const float* __restrict__ X,
                 float* __restrict__ Cm, const float* __restrict__ Res,
                 int M, int N, int K,
                 long wB, long xB, long cB)
{
    const int b = blockIdx.z;
    const float* Wb = Wt + (size_t)b * wB;
    const float* Xb = X  + (size_t)b * xB;
    float*       Cb = Cm + (size_t)b * cB;
    const float* Rb = Res ? (Res + (size_t)b * cB) : nullptr;

    __shared__ unsigned As[BK][BM + 8];   // [k][m], tf32 bits
    __shared__ unsigned Bs[BK][BN + 8];   // [k][n], tf32 bits

    const int tid  = threadIdx.x;
    const int lane = tid & 31, warp = tid >> 5;
    const int wm = warp & 3;              // 0..3 -> m offset wm*32
    const int wn = warp >> 2;             // 0..1 -> n offset wn*64
    const int g  = lane >> 2;             // group 0..7
    const int tg = lane & 3;              // thread-in-group 0..3

    const int m0 = blockIdx.y * BM;
    const int n0 = blockIdx.x * BN;

    float acc[2][8][4];
    #pragma unroll
    for (int i = 0; i < 2; i++)
        #pragma unroll
        for (int j = 0; j < 8; j++)
            #pragma unroll
            for (int q = 0; q < 4; q++) acc[i][j][q] = 0.f;

    // A load: thread -> row ar (0..127), k-cols ac..ac+7 (scalar, guarded)
    const int ar = tid >> 1;
    const int ac = (tid & 1) * 8;
    // B load: 2 float4 per thread over the 16x128 tile
    float  aR[8];
    float4 bR[2];

    auto nothing = 0; (void)nothing;

    // prefetch k0 = 0
    {
        #pragma unroll
        for (int i = 0; i < 8; i++) {
            int mm = m0 + ar, kk = ac + i;
            aR[i] = (mm < M && kk < K) ? Wb[(size_t)mm * K + kk] : 0.f;
        }
        #pragma unroll
        for (int i = 0; i < 2; i++) {
            int q = tid + i * 256;
            int kr = q >> 5, c4 = (q & 31) * 4;
            if (kr < K) bR[i] = *(const float4*)&Xb[(size_t)kr * N + n0 + c4];
            else        bR[i] = make_float4(0.f, 0.f, 0.f, 0.f);
        }
    }

    for (int k0 = 0; k0 < K; k0 += BK) {
        // commit prefetched regs to smem (with tf32 conversion)
        #pragma unroll
        for (int i = 0; i < 8; i++) As[ac + i][ar] = f2tf(aR[i]);
        #pragma unroll
        for (int i = 0; i < 2; i++) {
            int q = tid + i * 256;
            int kr = q >> 5, c4 = (q & 31) * 4;
            Bs[kr][c4 + 0] = f2tf(bR[i].x);
            Bs[kr][c4 + 1] = f2tf(bR[i].y);
            Bs[kr][c4 + 2] = f2tf(bR[i].z);
            Bs[kr][c4 + 3] = f2tf(bR[i].w);
        }
        __syncthreads();

        // prefetch next tile
        if (k0 + BK < K) {
            #pragma unroll
            for (int i = 0; i < 8; i++) {
                int mm = m0 + ar, kk = k0 + BK + ac + i;
                aR[i] = (mm < M && kk < K) ? Wb[(size_t)mm * K + kk] : 0.f;
            }
            #pragma unroll
            for (int i = 0; i < 2; i++) {
                int q = tid + i * 256;
                int kr = k0 + BK + (q >> 5), c4 = (q & 31) * 4;
                if (kr < K) bR[i] = *(const float4*)&Xb[(size_t)kr * N + n0 + c4];
                else        bR[i] = make_float4(0.f, 0.f, 0.f, 0.f);
            }
        }

        // compute on the committed tile
        #pragma unroll
        for (int kk = 0; kk < 2; kk++) {
            const int kb = kk * 8;
            unsigned af[2][4], bf[8][2];
            #pragma unroll
            for (int i = 0; i < 2; i++) {
                int r = wm * 32 + i * 16;
                af[i][0] = As[kb + tg    ][r + g    ];
                af[i][1] = As[kb + tg    ][r + g + 8];
                af[i][2] = As[kb + tg + 4][r + g    ];
                af[i][3] = As[kb + tg + 4][r + g + 8];
            }
            #pragma unroll
            for (int j = 0; j < 8; j++) {
                int cn = wn * 64 + j * 8 + g;
                bf[j][0] = Bs[kb + tg    ][cn];
                bf[j][1] = Bs[kb + tg + 4][cn];
            }
            #pragma unroll
            for (int i = 0; i < 2; i++)
                #pragma unroll
                for (int j = 0; j < 8; j++)
                    mma_tf32(acc[i][j], af[i], bf[j]);
        }
        __syncthreads();
    }

    // Epilogue: optional residual add, float2 stores
    #pragma unroll
    for (int i = 0; i < 2; i++) {
        int r0 = m0 + wm * 32 + i * 16 + g;
        #pragma unroll
        for (int j = 0; j < 8; j++) {
            int cc = n0 + wn * 64 + j * 8 + tg * 2;
            if (r0 < M) {
                size_t o = (size_t)r0 * N + cc;
                float2 v = make_float2(acc[i][j][0], acc[i][j][1]);
                if (Rb) { float2 r = *(const float2*)&Rb[o]; v.x += r.x; v.y += r.y; }
                *(float2*)&Cb[o] = v;
            }
            if (r0 + 8 < M) {
                size_t o = (size_t)(r0 + 8) * N + cc;
                float2 v = make_float2(acc[i][j][2], acc[i][j][3]);
                if (Rb) { float2 r = *(const float2*)&Rb[o]; v.x += r.x; v.y += r.y; }
                *(float2*)&Cb[o] = v;
            }
        }
    }
}

// ---------------------------------------------------------------------------
// Depthwise 3x3 helper
// ---------------------------------------------------------------------------
__device__ __forceinline__ float dw3x3(const float* __restrict__ ip,
                                       const float* __restrict__ wc,
                                       int x, int y)
{
    float s = 0.f;
    #pragma unroll
    for (int dy = -1; dy <= 1; dy++) {
        int yy = y + dy;
        if (yy < 0 || yy >= Hh) continue;
        #pragma unroll
        for (int dx = -1; dx <= 1; dx++) {
            int xx = x + dx;
            if (xx < 0 || xx >= Wd) continue;
            s += wc[(dy + 1) * 3 + (dx + 1)] * ip[yy * Wd + xx];
        }
    }
    return s;
}

// ---------------------------------------------------------------------------
// qkv depthwise conv + fused q/k sum-of-squares (block covers 256 px of one ch)
// ---------------------------------------------------------------------------
__global__ void dwconv_qkv_kernel(const float* __restrict__ in,
                                  const float* __restrict__ w,
                                  float* __restrict__ out)
{
    size_t idx = (size_t)blockIdx.x * 256 + threadIdx.x;
    int pix = (int)(idx & (HW - 1));
    size_t bc = idx >> 14;
    int b = (int)(bc / C3);
    int c = (int)(bc % C3);
    int x = pix & (Wd - 1);
    int y = pix >> 7;
    const float* ip = in + (bc << 14);
    float s = dw3x3(ip, w + (size_t)c * 9, x, y);
    out[idx] = s;

    // fused sum of squares for q (c<192) and k (192<=c<384)
    __shared__ float red[256];
    red[threadIdx.x] = (c < 2 * C) ? s * s : 0.f;
    __syncthreads();
    #pragma unroll
    for (int st = 128; st > 0; st >>= 1) {
        if (threadIdx.x < st) red[threadIdx.x] += red[threadIdx.x + st];
        __syncthreads();
    }
    if (threadIdx.x == 0 && c < 2 * C)
        atomicAdd(&g_sq[b * 2 * C + c], red[0]);
}

// ---------------------------------------------------------------------------
// FFN depthwise conv + fused gelu gate: out[j] = gelu(dw(x[j])) * dw(x[j+510])
// ---------------------------------------------------------------------------
__global__ void dwgate_kernel(const float* __restrict__ in,
                              const float* __restrict__ w,
                              float* __restrict__ out)
{
    size_t idx = (size_t)blockIdx.x * 256 + threadIdx.x;
    size_t total = (size_t)Bq * HIDDEN * HW;
    if (idx >= total) return;
    int pix = (int)(idx & (HW - 1));
    size_t bc = idx >> 14;
    int b = (int)(bc / HIDDEN);
    int j = (int)(bc % HIDDEN);
    int x = pix & (Wd - 1);
    int y = pix >> 7;
    const float* ip1 = in + ((size_t)b * FF2 + j) * HW;
    const float* ip2 = in + ((size_t)b * FF2 + HIDDEN + j) * HW;
    float s1 = dw3x3(ip1, w + (size_t)j * 9, x, y);
    float s2 = dw3x3(ip2, w + (size_t)(HIDDEN + j) * 9, x, y);
    float gl = 0.5f * s1 * (1.f + erff(s1 * 0.70710678118654752f));
    out[idx] = gl * s2;
}

// ---------------------------------------------------------------------------
// zero accumulators (attn grams + sumsq)
// ---------------------------------------------------------------------------
__global__ void zero_kernel()
{
    int i = blockIdx.x * 256 + threadIdx.x;
    if (i < Bq * HEADS * HD * HD) g_attn[i] = 0.f;
    if (i < Bq * 2 * C) g_sq[i] = 0.f;
}

// ---------------------------------------------------------------------------
// finalize inverse l2 norms
// ---------------------------------------------------------------------------
__global__ void invfin_kernel()
{
    int i = blockIdx.x * 256 + threadIdx.x;
    if (i >= Bq * 2 * C) return;
    int b = i / (2 * C), c = i % (2 * C);
    float inv = 1.f / fmaxf(sqrtf(g_sq[i]), 1e-12f);
    if (c < C) g_invq[b * C + c] = inv;
    else       g_invk[b * C + c - C] = inv;
}

// ---------------------------------------------------------------------------
// Gram matrices (split-K atomics): attn[b,h,d,c] = sum_p q[d,p] k[c,p]
// ---------------------------------------------------------------------------
#define GSPLIT 16
#define GBK    128
__global__ void gram_kernel()
{
    int bh = blockIdx.x;
    int split = blockIdx.y;
    int b = bh >> 3, h = bh & 7;
    const float* qbase = g_t2 + ((size_t)b * C3 + h * HD) * HW;
    const float* kbase = g_t2 + ((size_t)b * C3 + C + h * HD) * HW;

    __shared__ float qs[HD][GBK + 4];
    __shared__ float ks[HD][GBK + 4];

    int tid = threadIdx.x;
    int tx = tid & 7, ty = tid >> 3;
    float acc[3][3] = {{0.f}};

    int p0 = split * (HW / GSPLIT);
    for (int t = 0; t < (HW / GSPLIT) / GBK; t++) {
        int pb = p0 + t * GBK;
        for (int i = tid; i < 2 * HD * GBK; i += 64) {
            int r = i >> 7, k = i & (GBK - 1);
            if (r < HD) qs[r][k]      = qbase[(size_t)r * HW + pb + k];
            else        ks[r - HD][k] = kbase[(size_t)(r - HD) * HW + pb + k];
        }
        __syncthreads();
        #pragma unroll 4
        for (int k = 0; k < GBK; k++) {
            float qv[3], kv[3];
            #pragma unroll
            for (int ii = 0; ii < 3; ii++) qv[ii] = qs[ty * 3 + ii][k];
            #pragma unroll
            for (int jj = 0; jj < 3; jj++) kv[jj] = ks[tx * 3 + jj][k];
            #pragma unroll
            for (int ii = 0; ii < 3; ii++)
                #pragma unroll
                for (int jj = 0; jj < 3; jj++) acc[ii][jj] += qv[ii] * kv[jj];
        }
        __syncthreads();
    }
    float* dst = g_attn + (size_t)bh * HD * HD;
    #pragma unroll
    for (int ii = 0; ii < 3; ii++)
        #pragma unroll
        for (int jj = 0; jj < 3; jj++)
            atomicAdd(&dst[(ty * 3 + ii) * HD + tx * 3 + jj], acc[ii][jj]);
}

// ---------------------------------------------------------------------------
// Softmax per row, fused l2norm scaling + temperature
// ---------------------------------------------------------------------------
__global__ void softmax_kernel(const float* __restrict__ temp)
{
    int bh = blockIdx.x;
    int b = bh >> 3, h = bh & 7;
    int i = threadIdx.x;
    if (i >= HD) return;
    float* row = g_attn + (size_t)bh * HD * HD + i * HD;
    float qi = g_invq[b * C + h * HD + i] * temp[h];
    float vals[HD];
    float mx = -1e30f;
    #pragma unroll
    for (int j = 0; j < HD; j++) {
        float v = row[j] * qi * g_invk[b * C + h * HD + j];
        vals[j] = v;
        mx = fmaxf(mx, v);
    }
    float s = 0.f;
    #pragma unroll
    for (int j = 0; j < HD; j++) { vals[j] = expf(vals[j] - mx); s += vals[j]; }
    float inv = 1.f / s;
    #pragma unroll
    for (int j = 0; j < HD; j++) row[j] = vals[j] * inv;
}

// ---------------------------------------------------------------------------
// wm[b][o][h*HD+c] = sum_d W_proj[o][h*HD+d] * attn[b,h,d,c]
// ---------------------------------------------------------------------------
__global__ void wm_kernel(const float* __restrict__ wproj)
{
    int idx = blockIdx.x * 256 + threadIdx.x;
    if (idx >= Bq * C * C) return;
    int cc = idx % C;
    int o  = (idx / C) % C;
    int b  = idx / (C * C);
    int h = cc / HD, ci = cc % HD;
    const float* wrow = wproj + (size_t)o * C + h * HD;
    const float* arow = g_attn + ((size_t)(b * HEADS + h) * HD) * HD + ci;
    float s = 0.f;
    #pragma unroll
    for (int d = 0; d < HD; d++) s += wrow[d] * arow[d * HD];
    g_wm[idx] = s;
}

// ---------------------------------------------------------------------------
// Launch sequence
// ---------------------------------------------------------------------------
extern "C" void kernel_launch(void* const* d_in, const int* in_sizes, int n_in,
                              void* d_out, int out_size)
{
    const float* x      = (const float*)d_in[0];
    const float* temp   = (const float*)d_in[1];
    const float* ln1w   = (const float*)d_in[2];
    const float* ln1b   = (const float*)d_in[3];
    const float* ln2w   = (const float*)d_in[4];
    const float* ln2b   = (const float*)d_in[5];
    const float* w_qkv  = (const float*)d_in[6];
    const float* w_qkvd = (const float*)d_in[7];
    const float* w_proj = (const float*)d_in[8];
    const float* w_in   = (const float*)d_in[9];
    const float* w_dw   = (const float*)d_in[10];
    const float* w_out  = (const float*)d_in[11];
    float* out = (float*)d_out;

    float *p_ln, *p_t1, *p_t2, *p_xmid, *p_wm;
    cudaGetSymbolAddress((void**)&p_ln,   g_ln);
    cudaGetSymbolAddress((void**)&p_t1,   g_t1);
    cudaGetSymbolAddress((void**)&p_t2,   g_t2);
    cudaGetSymbolAddress((void**)&p_xmid, g_xmid);
    cudaGetSymbolAddress((void**)&p_wm,   g_wm);

    const long sC   = (long)C * HW;
    const long sC3  = (long)C3 * HW;
    const long sFF2 = (long)FF2 * HW;
    const long sHID = (long)HIDDEN * HW;

    // 1. ln1(x) -> g_ln
    ln_kernel<<<(Bq * HW + 255) / 256, 256>>>(x, ln1w, ln1b, p_ln);

    // 2. qkv = W_qkv @ ln  (576 x 16384, K=192) -> g_t1   [tensor cores]
    tf32_gemm_kernel<<<dim3(HW / BN, (C3 + BM - 1) / BM, Bq), 256>>>(
        w_qkv, p_ln, p_t1, nullptr, C3, HW, C, 0, sC, sC3);

    // 3. zero accumulators
    zero_kernel<<<(Bq * HEADS * HD * HD + 255) / 256, 256>>>();

    // 4. qkv depthwise 3x3 + fused q/k sumsq -> g_t2
    {
        size_t total = (size_t)Bq * C3 * HW;
        dwconv_qkv_kernel<<<(unsigned)(total / 256), 256>>>(p_t1, w_qkvd, p_t2);
    }

    // 5. finalize inverse norms
    invfin_kernel<<<(Bq * 2 * C + 255) / 256, 256>>>();

    // 6. q @ k^T gram matrices
    gram_kernel<<<dim3(Bq * HEADS, GSPLIT), 64>>>();

    // 7. softmax (fused normalization + temperature)
    softmax_kernel<<<Bq * HEADS, 32>>>(temp);

    // 8. wm = W_proj @ blockdiag(attn)
    wm_kernel<<<(Bq * C * C + 255) / 256, 256>>>(w_proj);

    // 9. xmid = wm @ v + x   [tensor cores]
    tf32_gemm_kernel<<<dim3(HW / BN, (C + BM - 1) / BM, Bq), 256>>>(
        p_wm, p_t2 + (size_t)2 * C * HW, p_xmid, x,
        C, HW, C, (long)C * C, sC3, sC);

    // 10. ln2(xmid) -> g_ln
    ln_kernel<<<(Bq * HW + 255) / 256, 256>>>(p_xmid, ln2w, ln2b, p_ln);

    // 11. ffn hidden = W_in @ ln  (1020 x 16384, K=192) -> g_t1  [tensor cores]
    tf32_gemm_kernel<<<dim3(HW / BN, (FF2 + BM - 1) / BM, Bq), 256>>>(
        w_in, p_ln, p_t1, nullptr, FF2, HW, C, 0, sC, sFF2);

    // 12. fused depthwise 3x3 + gelu gate -> g_t2 (HIDDEN ch per batch)
    {
        size_t total = (size_t)Bq * HIDDEN * HW;
        dwgate_kernel<<<(unsigned)((total + 255) / 256), 256>>>(p_t1, w_dw, p_t2);
    }

    // 13. out = W_out @ gated + xmid  (192 x 16384, K=510)  [tensor cores]
    tf32_gemm_kernel<<<dim3(HW / BN, (C + BM - 1) / BM, Bq), 256>>>(
        w_out, p_t2, out, p_xmid, C, HW, HIDDEN, 0, sHID, sC);
}

// round 7
// speedup vs baseline: 2.5931x; 1.2711x over previous
#include <cuda_runtime.h>
#include <math.h>

// Problem constants
#define Bq      4
#define C       192
#define C3      576       // 3*C (qkv channels)
#define HEADS   8
#define HD      24        // head dim
#define HIDDEN  510
#define FF2     1020      // 2*HIDDEN
#define Hh      128
#define Wd      128
#define HW      16384
#define EPS_LN  1e-5f

// ---------------------------------------------------------------------------
// Static scratch
// ---------------------------------------------------------------------------
__device__ float g_ln  [(size_t)Bq * C   * HW];
__device__ float g_t1  [(size_t)Bq * FF2 * HW];
__device__ float g_t2  [(size_t)Bq * FF2 * HW];
__device__ float g_xmid[(size_t)Bq * C   * HW];
__device__ float g_wm  [Bq * C * C];
__device__ float g_attn[Bq * HEADS * HD * HD];
__device__ float g_sq  [Bq * 2 * C];
__device__ float g_invq[Bq * C];
__device__ float g_invk[Bq * C];

// ---------------------------------------------------------------------------
// LayerNorm over channel dim (per pixel), NCHW
// ---------------------------------------------------------------------------
__global__ void ln_kernel(const float* __restrict__ x, const float* __restrict__ w,
                          const float* __restrict__ bias, float* __restrict__ out)
{
    int idx = blockIdx.x * blockDim.x + threadIdx.x;
    if (idx >= Bq * HW) return;
    int b = idx >> 14;
    int pix = idx & (HW - 1);
    const float* xp = x + (size_t)b * C * HW + pix;
    float s = 0.f, s2 = 0.f;
    #pragma unroll 8
    for (int c = 0; c < C; c++) {
        float v = xp[(size_t)c * HW];
        s += v; s2 += v * v;
    }
    float mu  = s * (1.f / C);
    float var = s2 * (1.f / C) - mu * mu;
    float r   = rsqrtf(var + EPS_LN);
    float* op = out + (size_t)b * C * HW + pix;
    #pragma unroll 8
    for (int c = 0; c < C; c++)
        op[(size_t)c * HW] = (xp[(size_t)c * HW] - mu) * r * w[c] + bias[c];
}

// ---------------------------------------------------------------------------
// TF32 tensor-core GEMM: C[b] (MxN) = W[b] (MxK) @ X[b] (KxN) (+ Res[b])
// ---------------------------------------------------------------------------
#define BM 128
#define BN 128
#define BK 16

__device__ __forceinline__ unsigned f2tf(float f)
{
    unsigned u;
    asm("cvt.rna.tf32.f32 %0, %1;" : "=r"(u) : "f"(f));
    return u;
}

__device__ __forceinline__ void mma_tf32(float c[4], const unsigned a[4], const unsigned b[2])
{
    asm volatile(
        "mma.sync.aligned.m16n8k8.row.col.f32.tf32.tf32.f32 "
        "{%0,%1,%2,%3}, {%4,%5,%6,%7}, {%8,%9}, {%0,%1,%2,%3};"
        : "+f"(c[0]), "+f"(c[1]), "+f"(c[2]), "+f"(c[3])
        : "r"(a[0]), "r"(a[1]), "r"(a[2]), "r"(a[3]), "r"(b[0]), "r"(b[1]));
}

__global__ void __launch_bounds__(256, 2)
tf32_gemm_kernel(const float* __restrict__ Wt, const float* __restrict__ X,
                 float* __restrict__ Cm, const float* __restrict__ Res,
                 int M, int N, int K,
                 long wB, long xB, long cB)
{
    const int b = blockIdx.z;
    const float* Wb = Wt + (size_t)b * wB;
    const float* Xb = X  + (size_t)b * xB;
    float*       Cb = Cm + (size_t)b * cB;
    const float* Rb = Res ? (Res + (size_t)b * cB) : nullptr;

    __shared__ unsigned As[BK][BM + 8];
    __shared__ unsigned Bs[BK][BN + 8];

    const int tid  = threadIdx.x;
    const int lane = tid & 31, warp = tid >> 5;
    const int wm = warp & 3;
    const int wn = warp >> 2;
    const int g  = lane >> 2;
    const int tg = lane & 3;

    const int m0 = blockIdx.y * BM;
    const int n0 = blockIdx.x * BN;

    float acc[2][8][4];
    #pragma unroll
    for (int i = 0; i < 2; i++)
        #pragma unroll
        for (int j = 0; j < 8; j++)
            #pragma unroll
            for (int q = 0; q < 4; q++) acc[i][j][q] = 0.f;

    const int ar = tid >> 1;
    const int ac = (tid & 1) * 8;
    float  aR[8];
    float4 bR[2];

    {
        #pragma unroll
        for (int i = 0; i < 8; i++) {
            int mm = m0 + ar, kk = ac + i;
            aR[i] = (mm < M && kk < K) ? Wb[(size_t)mm * K + kk] : 0.f;
        }
        #pragma unroll
        for (int i = 0; i < 2; i++) {
            int q = tid + i * 256;
            int kr = q >> 5, c4 = (q & 31) * 4;
            if (kr < K) bR[i] = *(const float4*)&Xb[(size_t)kr * N + n0 + c4];
            else        bR[i] = make_float4(0.f, 0.f, 0.f, 0.f);
        }
    }

    for (int k0 = 0; k0 < K; k0 += BK) {
        #pragma unroll
        for (int i = 0; i < 8; i++) As[ac + i][ar] = f2tf(aR[i]);
        #pragma unroll
        for (int i = 0; i < 2; i++) {
            int q = tid + i * 256;
            int kr = q >> 5, c4 = (q & 31) * 4;
            Bs[kr][c4 + 0] = f2tf(bR[i].x);
            Bs[kr][c4 + 1] = f2tf(bR[i].y);
            Bs[kr][c4 + 2] = f2tf(bR[i].z);
            Bs[kr][c4 + 3] = f2tf(bR[i].w);
        }
        __syncthreads();

        if (k0 + BK < K) {
            #pragma unroll
            for (int i = 0; i < 8; i++) {
                int mm = m0 + ar, kk = k0 + BK + ac + i;
                aR[i] = (mm < M && kk < K) ? Wb[(size_t)mm * K + kk] : 0.f;
            }
            #pragma unroll
            for (int i = 0; i < 2; i++) {
                int q = tid + i * 256;
                int kr = k0 + BK + (q >> 5), c4 = (q & 31) * 4;
                if (kr < K) bR[i] = *(const float4*)&Xb[(size_t)kr * N + n0 + c4];
                else        bR[i] = make_float4(0.f, 0.f, 0.f, 0.f);
            }
        }

        #pragma unroll
        for (int kk = 0; kk < 2; kk++) {
            const int kb = kk * 8;
            unsigned af[2][4], bf[8][2];
            #pragma unroll
            for (int i = 0; i < 2; i++) {
                int r = wm * 32 + i * 16;
                af[i][0] = As[kb + tg    ][r + g    ];
                af[i][1] = As[kb + tg    ][r + g + 8];
                af[i][2] = As[kb + tg + 4][r + g    ];
                af[i][3] = As[kb + tg + 4][r + g + 8];
            }
            #pragma unroll
            for (int j = 0; j < 8; j++) {
                int cn = wn * 64 + j * 8 + g;
                bf[j][0] = Bs[kb + tg    ][cn];
                bf[j][1] = Bs[kb + tg + 4][cn];
            }
            #pragma unroll
            for (int i = 0; i < 2; i++)
                #pragma unroll
                for (int j = 0; j < 8; j++)
                    mma_tf32(acc[i][j], af[i], bf[j]);
        }
        __syncthreads();
    }

    #pragma unroll
    for (int i = 0; i < 2; i++) {
        int r0 = m0 + wm * 32 + i * 16 + g;
        #pragma unroll
        for (int j = 0; j < 8; j++) {
            int cc = n0 + wn * 64 + j * 8 + tg * 2;
            if (r0 < M) {
                size_t o = (size_t)r0 * N + cc;
                float2 v = make_float2(acc[i][j][0], acc[i][j][1]);
                if (Rb) { float2 r = *(const float2*)&Rb[o]; v.x += r.x; v.y += r.y; }
                *(float2*)&Cb[o] = v;
            }
            if (r0 + 8 < M) {
                size_t o = (size_t)(r0 + 8) * N + cc;
                float2 v = make_float2(acc[i][j][2], acc[i][j][3]);
                if (Rb) { float2 r = *(const float2*)&Rb[o]; v.x += r.x; v.y += r.y; }
                *(float2*)&Cb[o] = v;
            }
        }
    }
}

// ---------------------------------------------------------------------------
// Tiled depthwise 3x3 machinery
// Block = 256 threads; strip = 32 rows x 128 cols of one channel.
// Smem halo tile 34x128; each thread computes 16 rows of one column with a
// sliding 3x3 register window (3 LDS + 9 FFMA per output).
// ---------------------------------------------------------------------------
#define SROWS 32

__device__ __forceinline__ void load_tile(float (*tile)[Wd],
                                          const float* __restrict__ ip,
                                          int r0, int tid)
{
    #pragma unroll
    for (int i = tid; i < 34 * 32; i += 256) {
        int rr = i >> 5, cg = (i & 31) << 2;
        int gr = r0 + rr;
        float4 v = make_float4(0.f, 0.f, 0.f, 0.f);
        if (gr >= 0 && gr < Hh) v = *(const float4*)&ip[gr * Wd + cg];
        *(float4*)&tile[rr][cg] = v;
    }
}

__device__ __forceinline__ void ldrow(const float (*tile)[Wd], int r, int tx,
                                      float& m, float& c, float& p)
{
    c = tile[r][tx];
    m = (tx > 0)      ? tile[r][tx - 1] : 0.f;
    p = (tx < Wd - 1) ? tile[r][tx + 1] : 0.f;
}

// ---------------------------------------------------------------------------
// qkv depthwise conv + fused q/k sum-of-squares
// grid.x = Bq*C3*4 (4 strips per channel)
// ---------------------------------------------------------------------------
__global__ void __launch_bounds__(256)
dwconv_qkv_kernel(const float* __restrict__ in, const float* __restrict__ w,
                  float* __restrict__ out)
{
    __shared__ float tile[34][Wd];
    __shared__ float red[256];

    int strip = blockIdx.x & 3;
    int bc    = blockIdx.x >> 2;         // b*C3 + c
    int c = bc % C3;
    int b = bc / C3;
    int tid = threadIdx.x;

    const float* ip = in + ((size_t)bc << 14);
    load_tile(tile, ip, strip * SROWS - 1, tid);

    float wreg[9];
    #pragma unroll
    for (int i = 0; i < 9; i++) wreg[i] = __ldg(&w[(size_t)c * 9 + i]);
    __syncthreads();

    int tx   = tid & 127;
    int tseg = tid >> 7;                 // 0..1, 16 rows each
    int rb   = tseg * 16;                // local output row base

    float t0m, t0c, t0p, t1m, t1c, t1p, t2m, t2c, t2p;
    ldrow(tile, rb,     tx, t0m, t0c, t0p);
    ldrow(tile, rb + 1, tx, t1m, t1c, t1p);

    float* op = out + ((size_t)bc << 14) + (strip * SROWS + rb) * Wd + tx;
    float sq = 0.f;

    #pragma unroll
    for (int rr = 0; rr < 16; rr++) {
        ldrow(tile, rb + rr + 2, tx, t2m, t2c, t2p);
        float s = wreg[0] * t0m + wreg[1] * t0c + wreg[2] * t0p
                + wreg[3] * t1m + wreg[4] * t1c + wreg[5] * t1p
                + wreg[6] * t2m + wreg[7] * t2c + wreg[8] * t2p;
        op[rr * Wd] = s;
        sq += s * s;
        t0m = t1m; t0c = t1c; t0p = t1p;
        t1m = t2m; t1c = t2c; t1p = t2p;
    }

    // fused sum of squares for q (c<192) and k (192<=c<384)
    if (c < 2 * C) {
        red[tid] = sq;
        __syncthreads();
        #pragma unroll
        for (int st = 128; st > 0; st >>= 1) {
            if (tid < st) red[tid] += red[tid + st];
            __syncthreads();
        }
        if (tid == 0) atomicAdd(&g_sq[b * 2 * C + c], red[0]);
    }
}

// ---------------------------------------------------------------------------
// FFN depthwise conv + fused gelu gate (both channels j, j+510 in one block)
// grid.x = Bq*HIDDEN*4
// ---------------------------------------------------------------------------
__global__ void __launch_bounds__(256)
dwgate_kernel(const float* __restrict__ in, const float* __restrict__ w,
              float* __restrict__ out)
{
    __shared__ float tileA[34][Wd];
    __shared__ float tileB[34][Wd];

    int strip = blockIdx.x & 3;
    int bj    = blockIdx.x >> 2;         // b*HIDDEN + j
    int j = bj % HIDDEN;
    int b = bj / HIDDEN;
    int tid = threadIdx.x;

    const float* ip1 = in + (((size_t)b * FF2 + j) << 14);
    const float* ip2 = in + (((size_t)b * FF2 + HIDDEN + j) << 14);
    int r0 = strip * SROWS - 1;
    load_tile(tileA, ip1, r0, tid);
    load_tile(tileB, ip2, r0, tid);

    float wa[9], wb[9];
    #pragma unroll
    for (int i = 0; i < 9; i++) {
        wa[i] = __ldg(&w[(size_t)j * 9 + i]);
        wb[i] = __ldg(&w[(size_t)(HIDDEN + j) * 9 + i]);
    }
    __syncthreads();

    int tx   = tid & 127;
    int tseg = tid >> 7;
    int rb   = tseg * 16;

    float a0m, a0c, a0p, a1m, a1c, a1p, a2m, a2c, a2p;
    float b0m, b0c, b0p, b1m, b1c, b1p, b2m, b2c, b2p;
    ldrow(tileA, rb,     tx, a0m, a0c, a0p);
    ldrow(tileA, rb + 1, tx, a1m, a1c, a1p);
    ldrow(tileB, rb,     tx, b0m, b0c, b0p);
    ldrow(tileB, rb + 1, tx, b1m, b1c, b1p);

    float* op = out + (((size_t)b * HIDDEN + j) << 14) + (strip * SROWS + rb) * Wd + tx;

    #pragma unroll
    for (int rr = 0; rr < 16; rr++) {
        ldrow(tileA, rb + rr + 2, tx, a2m, a2c, a2p);
        ldrow(tileB, rb + rr + 2, tx, b2m, b2c, b2p);
        float s1 = wa[0] * a0m + wa[1] * a0c + wa[2] * a0p
                 + wa[3] * a1m + wa[4] * a1c + wa[5] * a1p
                 + wa[6] * a2m + wa[7] * a2c + wa[8] * a2p;
        float s2 = wb[0] * b0m + wb[1] * b0c + wb[2] * b0p
                 + wb[3] * b1m + wb[4] * b1c + wb[5] * b1p
                 + wb[6] * b2m + wb[7] * b2c + wb[8] * b2p;
        float gl = 0.5f * s1 * (1.f + erff(s1 * 0.70710678118654752f));
        op[rr * Wd] = gl * s2;
        a0m = a1m; a0c = a1c; a0p = a1p;
        a1m = a2m; a1c = a2c; a1p = a2p;
        b0m = b1m; b0c = b1c; b0p = b1p;
        b1m = b2m; b1c = b2c; b1p = b2p;
    }
}

// ---------------------------------------------------------------------------
// zero accumulators (attn grams + sumsq)
// ---------------------------------------------------------------------------
__global__ void zero_kernel()
{
    int i = blockIdx.x * 256 + threadIdx.x;
    if (i < Bq * HEADS * HD * HD) g_attn[i] = 0.f;
    if (i < Bq * 2 * C) g_sq[i] = 0.f;
}

// ---------------------------------------------------------------------------
// finalize inverse l2 norms
// ---------------------------------------------------------------------------
__global__ void invfin_kernel()
{
    int i = blockIdx.x * 256 + threadIdx.x;
    if (i >= Bq * 2 * C) return;
    int b = i / (2 * C), c = i % (2 * C);
    float inv = 1.f / fmaxf(sqrtf(g_sq[i]), 1e-12f);
    if (c < C) g_invq[b * C + c] = inv;
    else       g_invk[b * C + c - C] = inv;
}

// ---------------------------------------------------------------------------
// Gram matrices (split-K atomics): attn[b,h,d,c] = sum_p q[d,p] k[c,p]
// ---------------------------------------------------------------------------
#define GSPLIT 16
#define GBK    128
__global__ void gram_kernel()
{
    int bh = blockIdx.x;
    int split = blockIdx.y;
    int b = bh >> 3, h = bh & 7;
    const float* qbase = g_t2 + ((size_t)b * C3 + h * HD) * HW;
    const float* kbase = g_t2 + ((size_t)b * C3 + C + h * HD) * HW;

    __shared__ float qs[HD][GBK + 4];
    __shared__ float ks[HD][GBK + 4];

    int tid = threadIdx.x;
    int tx = tid & 7, ty = tid >> 3;
    float acc[3][3] = {{0.f}};

    int p0 = split * (HW / GSPLIT);
    for (int t = 0; t < (HW / GSPLIT) / GBK; t++) {
        int pb = p0 + t * GBK;
        for (int i = tid; i < 2 * HD * GBK; i += 64) {
            int r = i >> 7, k = i & (GBK - 1);
            if (r < HD) qs[r][k]      = qbase[(size_t)r * HW + pb + k];
            else        ks[r - HD][k] = kbase[(size_t)(r - HD) * HW + pb + k];
        }
        __syncthreads();
        #pragma unroll 4
        for (int k = 0; k < GBK; k++) {
            float qv[3], kv[3];
            #pragma unroll
            for (int ii = 0; ii < 3; ii++) qv[ii] = qs[ty * 3 + ii][k];
            #pragma unroll
            for (int jj = 0; jj < 3; jj++) kv[jj] = ks[tx * 3 + jj][k];
            #pragma unroll
            for (int ii = 0; ii < 3; ii++)
                #pragma unroll
                for (int jj = 0; jj < 3; jj++) acc[ii][jj] += qv[ii] * kv[jj];
        }
        __syncthreads();
    }
    float* dst = g_attn + (size_t)bh * HD * HD;
    #pragma unroll
    for (int ii = 0; ii < 3; ii++)
        #pragma unroll
        for (int jj = 0; jj < 3; jj++)
            atomicAdd(&dst[(ty * 3 + ii) * HD + tx * 3 + jj], acc[ii][jj]);
}

// ---------------------------------------------------------------------------
// Softmax per row, fused l2norm scaling + temperature
// ---------------------------------------------------------------------------
__global__ void softmax_kernel(const float* __restrict__ temp)
{
    int bh = blockIdx.x;
    int b = bh >> 3, h = bh & 7;
    int i = threadIdx.x;
    if (i >= HD) return;
    float* row = g_attn + (size_t)bh * HD * HD + i * HD;
    float qi = g_invq[b * C + h * HD + i] * temp[h];
    float vals[HD];
    float mx = -1e30f;
    #pragma unroll
    for (int j = 0; j < HD; j++) {
        float v = row[j] * qi * g_invk[b * C + h * HD + j];
        vals[j] = v;
        mx = fmaxf(mx, v);
    }
    float s = 0.f;
    #pragma unroll
    for (int j = 0; j < HD; j++) { vals[j] = expf(vals[j] - mx); s += vals[j]; }
    float inv = 1.f / s;
    #pragma unroll
    for (int j = 0; j < HD; j++) row[j] = vals[j] * inv;
}

// ---------------------------------------------------------------------------
// wm[b][o][h*HD+c] = sum_d W_proj[o][h*HD+d] * attn[b,h,d,c]
// ---------------------------------------------------------------------------
__global__ void wm_kernel(const float* __restrict__ wproj)
{
    int idx = blockIdx.x * 256 + threadIdx.x;
    if (idx >= Bq * C * C) return;
    int cc = idx % C;
    int o  = (idx / C) % C;
    int b  = idx / (C * C);
    int h = cc / HD, ci = cc % HD;
    const float* wrow = wproj + (size_t)o * C + h * HD;
    const float* arow = g_attn + ((size_t)(b * HEADS + h) * HD) * HD + ci;
    float s = 0.f;
    #pragma unroll
    for (int d = 0; d < HD; d++) s += wrow[d] * arow[d * HD];
    g_wm[idx] = s;
}

// ---------------------------------------------------------------------------
// Launch sequence
// ---------------------------------------------------------------------------
extern "C" void kernel_launch(void* const* d_in, const int* in_sizes, int n_in,
                              void* d_out, int out_size)
{
    const float* x      = (const float*)d_in[0];
    const float* temp   = (const float*)d_in[1];
    const float* ln1w   = (const float*)d_in[2];
    const float* ln1b   = (const float*)d_in[3];
    const float* ln2w   = (const float*)d_in[4];
    const float* ln2b   = (const float*)d_in[5];
    const float* w_qkv  = (const float*)d_in[6];
    const float* w_qkvd = (const float*)d_in[7];
    const float* w_proj = (const float*)d_in[8];
    const float* w_in   = (const float*)d_in[9];
    const float* w_dw   = (const float*)d_in[10];
    const float* w_out  = (const float*)d_in[11];
    float* out = (float*)d_out;

    float *p_ln, *p_t1, *p_t2, *p_xmid, *p_wm;
    cudaGetSymbolAddress((void**)&p_ln,   g_ln);
    cudaGetSymbolAddress((void**)&p_t1,   g_t1);
    cudaGetSymbolAddress((void**)&p_t2,   g_t2);
    cudaGetSymbolAddress((void**)&p_xmid, g_xmid);
    cudaGetSymbolAddress((void**)&p_wm,   g_wm);

    const long sC   = (long)C * HW;
    const long sC3  = (long)C3 * HW;
    const long sFF2 = (long)FF2 * HW;
    const long sHID = (long)HIDDEN * HW;

    // 1. ln1(x) -> g_ln
    ln_kernel<<<(Bq * HW + 255) / 256, 256>>>(x, ln1w, ln1b, p_ln);

    // 2. qkv = W_qkv @ ln  [tensor cores]
    tf32_gemm_kernel<<<dim3(HW / BN, (C3 + BM - 1) / BM, Bq), 256>>>(
        w_qkv, p_ln, p_t1, nullptr, C3, HW, C, 0, sC, sC3);

    // 3. zero accumulators
    zero_kernel<<<(Bq * HEADS * HD * HD + 255) / 256, 256>>>();

    // 4. tiled qkv depthwise 3x3 + fused q/k sumsq -> g_t2
    dwconv_qkv_kernel<<<Bq * C3 * 4, 256>>>(p_t1, w_qkvd, p_t2);

    // 5. finalize inverse norms
    invfin_kernel<<<(Bq * 2 * C + 255) / 256, 256>>>();

    // 6. q @ k^T gram matrices
    gram_kernel<<<dim3(Bq * HEADS, GSPLIT), 64>>>();

    // 7. softmax (fused normalization + temperature)
    softmax_kernel<<<Bq * HEADS, 32>>>(temp);

    // 8. wm = W_proj @ blockdiag(attn)
    wm_kernel<<<(Bq * C * C + 255) / 256, 256>>>(w_proj);

    // 9. xmid = wm @ v + x   [tensor cores]
    tf32_gemm_kernel<<<dim3(HW / BN, (C + BM - 1) / BM, Bq), 256>>>(
        p_wm, p_t2 + (size_t)2 * C * HW, p_xmid, x,
        C, HW, C, (long)C * C, sC3, sC);

    // 10. ln2(xmid) -> g_ln
    ln_kernel<<<(Bq * HW + 255) / 256, 256>>>(p_xmid, ln2w, ln2b, p_ln);

    // 11. ffn hidden = W_in @ ln  [tensor cores]
    tf32_gemm_kernel<<<dim3(HW / BN, (FF2 + BM - 1) / BM, Bq), 256>>>(
        w_in, p_ln, p_t1, nullptr, FF2, HW, C, 0, sC, sFF2);

    // 12. tiled depthwise 3x3 + gelu gate -> g_t2
    dwgate_kernel<<<Bq * HIDDEN * 4, 256>>>(p_t1, w_dw, p_t2);

    // 13. out = W_out @ gated + xmid  [tensor cores]
    tf32_gemm_kernel<<<dim3(HW / BN, (C + BM - 1) / BM, Bq), 256>>>(
        w_out, p_t2, out, p_xmid, C, HW, HIDDEN, 0, sHID, sC);
}

// round 8
// speedup vs baseline: 4.0252x; 1.5523x over previous
#include <cuda_runtime.h>
#include <cuda_bf16.h>
#include <math.h>

// Problem constants
#define Bq      4
#define C       192
#define C3      576
#define HEADS   8
#define HD      24
#define HIDDEN  510
#define FF2     1020
#define Hh      128
#define Wd      128
#define HW      16384
#define EPS_LN  1e-5f
#define KOUTP   512       // padded K for w_out (510 -> 512)

// ---------------------------------------------------------------------------
// Static scratch
// ---------------------------------------------------------------------------
__device__ float g_t1  [(size_t)Bq * FF2 * HW];   // qkv pre-dw / ffn pre-dw
__device__ float g_t2  [(size_t)Bq * C3  * HW];   // qkv post-dw (q,k,v)
__device__ float g_xmid[(size_t)Bq * C   * HW];
__device__ float g_attn[Bq * HEADS * HD * HD];
__device__ float g_sq  [Bq * 2 * C];
__device__ float g_invq[Bq * C];
__device__ float g_invk[Bq * C];

__device__ __nv_bfloat16 g_lnb [(size_t)Bq * C      * HW];  // LN output (bf16)
__device__ __nv_bfloat16 g_gate[(size_t)Bq * HIDDEN * HW];  // gated FFN (bf16)
__device__ __nv_bfloat16 g_wqkvb[C3 * C];
__device__ __nv_bfloat16 g_winb [FF2 * C];
__device__ __nv_bfloat16 g_woutb[C * KOUTP];
__device__ __nv_bfloat16 g_wmb  [Bq * C * C];

// ---------------------------------------------------------------------------
// Weight fp32 -> bf16 conversion (with K padding)
// ---------------------------------------------------------------------------
__global__ void convw_kernel(const float* __restrict__ src, __nv_bfloat16* __restrict__ dst,
                             int M, int K, int Kpad)
{
    int idx = blockIdx.x * 256 + threadIdx.x;
    if (idx >= M * Kpad) return;
    int m = idx / Kpad, k = idx % Kpad;
    dst[idx] = (k < K) ? __float2bfloat16(src[(size_t)m * K + k]) : __float2bfloat16(0.f);
}

// ---------------------------------------------------------------------------
// LayerNorm over channel dim (per pixel), NCHW -> bf16 output
// ---------------------------------------------------------------------------
__global__ void ln_kernel(const float* __restrict__ x, const float* __restrict__ w,
                          const float* __restrict__ bias, __nv_bfloat16* __restrict__ out)
{
    int idx = blockIdx.x * blockDim.x + threadIdx.x;
    if (idx >= Bq * HW) return;
    int b = idx >> 14;
    int pix = idx & (HW - 1);
    const float* xp = x + (size_t)b * C * HW + pix;
    float s = 0.f, s2 = 0.f;
    #pragma unroll 8
    for (int c = 0; c < C; c++) {
        float v = xp[(size_t)c * HW];
        s += v; s2 += v * v;
    }
    float mu  = s * (1.f / C);
    float var = s2 * (1.f / C) - mu * mu;
    float r   = rsqrtf(var + EPS_LN);
    __nv_bfloat16* op = out + (size_t)b * C * HW + pix;
    #pragma unroll 8
    for (int c = 0; c < C; c++)
        op[(size_t)c * HW] = __float2bfloat16((xp[(size_t)c * HW] - mu) * r * w[c] + bias[c]);
}

// ---------------------------------------------------------------------------
// BF16 tensor-core GEMM: C[b] (MxN) = W[b] (MxKpad) @ X[b] (KrealxN) (+ Res[b])
// W is bf16 (pre-converted, K padded). X is bf16 or fp32 (template).
// mma.sync.aligned.m16n8k16.row.col.f32.bf16.bf16.f32
// ---------------------------------------------------------------------------
#define BM 128
#define BN 128
#define BK 16

__device__ __forceinline__ unsigned pack_bf2(float lo, float hi)
{
    __nv_bfloat162 v = __floats2bfloat162_rn(lo, hi);
    return *(unsigned*)&v;
}

__device__ __forceinline__ void mma_bf16(float c[4], const unsigned a[4], const unsigned b[2])
{
    asm volatile(
        "mma.sync.aligned.m16n8k16.row.col.f32.bf16.bf16.f32 "
        "{%0,%1,%2,%3}, {%4,%5,%6,%7}, {%8,%9}, {%0,%1,%2,%3};"
        : "+f"(c[0]), "+f"(c[1]), "+f"(c[2]), "+f"(c[3])
        : "r"(a[0]), "r"(a[1]), "r"(a[2]), "r"(a[3]), "r"(b[0]), "r"(b[1]));
}

template<bool XBF16>
__global__ void __launch_bounds__(256, 2)
bf16_gemm_kernel(const __nv_bfloat16* __restrict__ Wt, const void* __restrict__ Xv,
                 float* __restrict__ Cm, const float* __restrict__ Res,
                 int M, int N, int Kpad, int Kreal,
                 long wB, long xB, long cB)
{
    const int b = blockIdx.z;
    const __nv_bfloat16* Wb = Wt + (size_t)b * wB;
    const __nv_bfloat16* Xh = XBF16 ? ((const __nv_bfloat16*)Xv + (size_t)b * xB) : nullptr;
    const float*         Xf = XBF16 ? nullptr : ((const float*)Xv + (size_t)b * xB);
    float*       Cb = Cm + (size_t)b * cB;
    const float* Rb = Res ? (Res + (size_t)b * cB) : nullptr;

    __shared__ unsigned As2[8][BM + 8];   // [k2][m] bf16x2 packed along k
    __shared__ unsigned Bs2[8][BN + 8];   // [k2][n]

    const int tid  = threadIdx.x;
    const int lane = tid & 31, warp = tid >> 5;
    const int wm = warp & 3;
    const int wn = warp >> 2;
    const int g  = lane >> 2;
    const int tg = lane & 3;

    const int m0 = blockIdx.y * BM;
    const int n0 = blockIdx.x * BN;

    float acc[2][8][4];
    #pragma unroll
    for (int i = 0; i < 2; i++)
        #pragma unroll
        for (int j = 0; j < 8; j++)
            #pragma unroll
            for (int q = 0; q < 4; q++) acc[i][j][q] = 0.f;

    // A: thread -> row ar, 8 consecutive k (one uint4 of bf16)
    const int ar  = tid >> 1;
    const int ac8 = (tid & 1) * 8;
    // B: thread -> pair-row kr2 = tid>>5, 4 n-cols at c4
    const int kr2 = tid >> 5;
    const int c4  = (tid & 31) * 4;

    uint4  aR = make_uint4(0, 0, 0, 0);
    uint2  uA = make_uint2(0, 0), uB = make_uint2(0, 0);
    float4 fA = make_float4(0.f, 0.f, 0.f, 0.f), fB = fA;

    // prefetch k0 = 0
    {
        if (m0 + ar < M) aR = *(const uint4*)&Wb[(size_t)(m0 + ar) * Kpad + ac8];
        else             aR = make_uint4(0, 0, 0, 0);
        int kr = 2 * kr2;
        if (XBF16) {
            uA = (kr     < Kreal) ? *(const uint2*)&Xh[(size_t)kr * N + n0 + c4]       : make_uint2(0, 0);
            uB = (kr + 1 < Kreal) ? *(const uint2*)&Xh[(size_t)(kr + 1) * N + n0 + c4] : make_uint2(0, 0);
        } else {
            fA = (kr     < Kreal) ? *(const float4*)&Xf[(size_t)kr * N + n0 + c4]       : make_float4(0.f, 0.f, 0.f, 0.f);
            fB = (kr + 1 < Kreal) ? *(const float4*)&Xf[(size_t)(kr + 1) * N + n0 + c4] : make_float4(0.f, 0.f, 0.f, 0.f);
        }
    }

    for (int k0 = 0; k0 < Kpad; k0 += BK) {
        // commit
        {
            unsigned* asp = &As2[ac8 >> 1][ar];
            asp[0 * (BM + 8)] = aR.x;
            asp[1 * (BM + 8)] = aR.y;
            asp[2 * (BM + 8)] = aR.z;
            asp[3 * (BM + 8)] = aR.w;
            unsigned* bsp = &Bs2[kr2][c4];
            if (XBF16) {
                bsp[0] = __byte_perm(uA.x, uB.x, 0x5410);
                bsp[1] = __byte_perm(uA.x, uB.x, 0x7632);
                bsp[2] = __byte_perm(uA.y, uB.y, 0x5410);
                bsp[3] = __byte_perm(uA.y, uB.y, 0x7632);
            } else {
                bsp[0] = pack_bf2(fA.x, fB.x);
                bsp[1] = pack_bf2(fA.y, fB.y);
                bsp[2] = pack_bf2(fA.z, fB.z);
                bsp[3] = pack_bf2(fA.w, fB.w);
            }
        }
        __syncthreads();

        // prefetch next
        if (k0 + BK < Kpad) {
            if (m0 + ar < M) aR = *(const uint4*)&Wb[(size_t)(m0 + ar) * Kpad + k0 + BK + ac8];
            else             aR = make_uint4(0, 0, 0, 0);
            int kr = k0 + BK + 2 * kr2;
            if (XBF16) {
                uA = (kr     < Kreal) ? *(const uint2*)&Xh[(size_t)kr * N + n0 + c4]       : make_uint2(0, 0);
                uB = (kr + 1 < Kreal) ? *(const uint2*)&Xh[(size_t)(kr + 1) * N + n0 + c4] : make_uint2(0, 0);
            } else {
                fA = (kr     < Kreal) ? *(const float4*)&Xf[(size_t)kr * N + n0 + c4]       : make_float4(0.f, 0.f, 0.f, 0.f);
                fB = (kr + 1 < Kreal) ? *(const float4*)&Xf[(size_t)(kr + 1) * N + n0 + c4] : make_float4(0.f, 0.f, 0.f, 0.f);
            }
        }

        // compute: one m16n8k16 step consumes all 16 k
        {
            unsigned af[2][4], bfr[8][2];
            #pragma unroll
            for (int i = 0; i < 2; i++) {
                int r = wm * 32 + i * 16;
                af[i][0] = As2[tg    ][r + g    ];
                af[i][1] = As2[tg    ][r + g + 8];
                af[i][2] = As2[tg + 4][r + g    ];
                af[i][3] = As2[tg + 4][r + g + 8];
            }
            #pragma unroll
            for (int j = 0; j < 8; j++) {
                int cn = wn * 64 + j * 8 + g;
                bfr[j][0] = Bs2[tg    ][cn];
                bfr[j][1] = Bs2[tg + 4][cn];
            }
            #pragma unroll
            for (int i = 0; i < 2; i++)
                #pragma unroll
                for (int j = 0; j < 8; j++)
                    mma_bf16(acc[i][j], af[i], bfr[j]);
        }
        __syncthreads();
    }

    // Epilogue: fp32 accumulators, optional fp32 residual, float2 stores
    #pragma unroll
    for (int i = 0; i < 2; i++) {
        int r0 = m0 + wm * 32 + i * 16 + g;
        #pragma unroll
        for (int j = 0; j < 8; j++) {
            int cc = n0 + wn * 64 + j * 8 + tg * 2;
            if (r0 < M) {
                size_t o = (size_t)r0 * N + cc;
                float2 v = make_float2(acc[i][j][0], acc[i][j][1]);
                if (Rb) { float2 r = *(const float2*)&Rb[o]; v.x += r.x; v.y += r.y; }
                *(float2*)&Cb[o] = v;
            }
            if (r0 + 8 < M) {
                size_t o = (size_t)(r0 + 8) * N + cc;
                float2 v = make_float2(acc[i][j][2], acc[i][j][3]);
                if (Rb) { float2 r = *(const float2*)&Rb[o]; v.x += r.x; v.y += r.y; }
                *(float2*)&Cb[o] = v;
            }
        }
    }
}

// ---------------------------------------------------------------------------
// Tiled depthwise 3x3 machinery (strip = 32 rows x 128 cols, smem halo 34x128)
// ---------------------------------------------------------------------------
#define SROWS 32

__device__ __forceinline__ void load_tile(float (*tile)[Wd],
                                          const float* __restrict__ ip,
                                          int r0, int tid)
{
    #pragma unroll
    for (int i = tid; i < 34 * 32; i += 256) {
        int rr = i >> 5, cg = (i & 31) << 2;
        int gr = r0 + rr;
        float4 v = make_float4(0.f, 0.f, 0.f, 0.f);
        if (gr >= 0 && gr < Hh) v = *(const float4*)&ip[gr * Wd + cg];
        *(float4*)&tile[rr][cg] = v;
    }
}

__device__ __forceinline__ void ldrow(const float (*tile)[Wd], int r, int tx,
                                      float& m, float& c, float& p)
{
    c = tile[r][tx];
    m = (tx > 0)      ? tile[r][tx - 1] : 0.f;
    p = (tx < Wd - 1) ? tile[r][tx + 1] : 0.f;
}

// ---------------------------------------------------------------------------
// qkv depthwise conv + fused q/k sum-of-squares (fp32 out)
// ---------------------------------------------------------------------------
__global__ void __launch_bounds__(256)
dwconv_qkv_kernel(const float* __restrict__ in, const float* __restrict__ w,
                  float* __restrict__ out)
{
    __shared__ float tile[34][Wd];
    __shared__ float red[256];

    int strip = blockIdx.x & 3;
    int bc    = blockIdx.x >> 2;
    int c = bc % C3;
    int b = bc / C3;
    int tid = threadIdx.x;

    const float* ip = in + ((size_t)bc << 14);
    load_tile(tile, ip, strip * SROWS - 1, tid);

    float wreg[9];
    #pragma unroll
    for (int i = 0; i < 9; i++) wreg[i] = __ldg(&w[(size_t)c * 9 + i]);
    __syncthreads();

    int tx   = tid & 127;
    int tseg = tid >> 7;
    int rb   = tseg * 16;

    float t0m, t0c, t0p, t1m, t1c, t1p, t2m, t2c, t2p;
    ldrow(tile, rb,     tx, t0m, t0c, t0p);
    ldrow(tile, rb + 1, tx, t1m, t1c, t1p);

    float* op = out + ((size_t)bc << 14) + (strip * SROWS + rb) * Wd + tx;
    float sq = 0.f;

    #pragma unroll
    for (int rr = 0; rr < 16; rr++) {
        ldrow(tile, rb + rr + 2, tx, t2m, t2c, t2p);
        float s = wreg[0] * t0m + wreg[1] * t0c + wreg[2] * t0p
                + wreg[3] * t1m + wreg[4] * t1c + wreg[5] * t1p
                + wreg[6] * t2m + wreg[7] * t2c + wreg[8] * t2p;
        op[rr * Wd] = s;
        sq += s * s;
        t0m = t1m; t0c = t1c; t0p = t1p;
        t1m = t2m; t1c = t2c; t1p = t2p;
    }

    if (c < 2 * C) {
        red[tid] = sq;
        __syncthreads();
        #pragma unroll
        for (int st = 128; st > 0; st >>= 1) {
            if (tid < st) red[tid] += red[tid + st];
            __syncthreads();
        }
        if (tid == 0) atomicAdd(&g_sq[b * 2 * C + c], red[0]);
    }
}

// ---------------------------------------------------------------------------
// FFN depthwise conv + fused gelu gate -> bf16 output
// ---------------------------------------------------------------------------
__global__ void __launch_bounds__(256)
dwgate_kernel(const float* __restrict__ in, const float* __restrict__ w,
              __nv_bfloat16* __restrict__ out)
{
    __shared__ float tileA[34][Wd];
    __shared__ float tileB[34][Wd];

    int strip = blockIdx.x & 3;
    int bj    = blockIdx.x >> 2;
    int j = bj % HIDDEN;
    int b = bj / HIDDEN;
    int tid = threadIdx.x;

    const float* ip1 = in + (((size_t)b * FF2 + j) << 14);
    const float* ip2 = in + (((size_t)b * FF2 + HIDDEN + j) << 14);
    int r0 = strip * SROWS - 1;
    load_tile(tileA, ip1, r0, tid);
    load_tile(tileB, ip2, r0, tid);

    float wa[9], wb[9];
    #pragma unroll
    for (int i = 0; i < 9; i++) {
        wa[i] = __ldg(&w[(size_t)j * 9 + i]);
        wb[i] = __ldg(&w[(size_t)(HIDDEN + j) * 9 + i]);
    }
    __syncthreads();

    int tx   = tid & 127;
    int tseg = tid >> 7;
    int rb   = tseg * 16;

    float a0m, a0c, a0p, a1m, a1c, a1p, a2m, a2c, a2p;
    float b0m, b0c, b0p, b1m, b1c, b1p, b2m, b2c, b2p;
    ldrow(tileA, rb,     tx, a0m, a0c, a0p);
    ldrow(tileA, rb + 1, tx, a1m, a1c, a1p);
    ldrow(tileB, rb,     tx, b0m, b0c, b0p);
    ldrow(tileB, rb + 1, tx, b1m, b1c, b1p);

    __nv_bfloat16* op = out + (((size_t)b * HIDDEN + j) << 14) + (strip * SROWS + rb) * Wd + tx;

    #pragma unroll
    for (int rr = 0; rr < 16; rr++) {
        ldrow(tileA, rb + rr + 2, tx, a2m, a2c, a2p);
        ldrow(tileB, rb + rr + 2, tx, b2m, b2c, b2p);
        float s1 = wa[0] * a0m + wa[1] * a0c + wa[2] * a0p
                 + wa[3] * a1m + wa[4] * a1c + wa[5] * a1p
                 + wa[6] * a2m + wa[7] * a2c + wa[8] * a2p;
        float s2 = wb[0] * b0m + wb[1] * b0c + wb[2] * b0p
                 + wb[3] * b1m + wb[4] * b1c + wb[5] * b1p
                 + wb[6] * b2m + wb[7] * b2c + wb[8] * b2p;
        float gl = 0.5f * s1 * (1.f + erff(s1 * 0.70710678118654752f));
        op[rr * Wd] = __float2bfloat16(gl * s2);
        a0m = a1m; a0c = a1c; a0p = a1p;
        a1m = a2m; a1c = a2c; a1p = a2p;
        b0m = b1m; b0c = b1c; b0p = b1p;
        b1m = b2m; b1c = b2c; b1p = b2p;
    }
}

// ---------------------------------------------------------------------------
// zero accumulators
// ---------------------------------------------------------------------------
__global__ void zero_kernel()
{
    int i = blockIdx.x * 256 + threadIdx.x;
    if (i < Bq * HEADS * HD * HD) g_attn[i] = 0.f;
    if (i < Bq * 2 * C) g_sq[i] = 0.f;
}

// ---------------------------------------------------------------------------
// finalize inverse l2 norms
// ---------------------------------------------------------------------------
__global__ void invfin_kernel()
{
    int i = blockIdx.x * 256 + threadIdx.x;
    if (i >= Bq * 2 * C) return;
    int b = i / (2 * C), c = i % (2 * C);
    float inv = 1.f / fmaxf(sqrtf(g_sq[i]), 1e-12f);
    if (c < C) g_invq[b * C + c] = inv;
    else       g_invk[b * C + c - C] = inv;
}

// ---------------------------------------------------------------------------
// Gram matrices (split-K atomics)
// ---------------------------------------------------------------------------
#define GSPLIT 16
#define GBK    128
__global__ void gram_kernel()
{
    int bh = blockIdx.x;
    int split = blockIdx.y;
    int b = bh >> 3, h = bh & 7;
    const float* qbase = g_t2 + ((size_t)b * C3 + h * HD) * HW;
    const float* kbase = g_t2 + ((size_t)b * C3 + C + h * HD) * HW;

    __shared__ float qs[HD][GBK + 4];
    __shared__ float ks[HD][GBK + 4];

    int tid = threadIdx.x;
    int tx = tid & 7, ty = tid >> 3;
    float acc[3][3] = {{0.f}};

    int p0 = split * (HW / GSPLIT);
    for (int t = 0; t < (HW / GSPLIT) / GBK; t++) {
        int pb = p0 + t * GBK;
        for (int i = tid; i < 2 * HD * GBK; i += 64) {
            int r = i >> 7, k = i & (GBK - 1);
            if (r < HD) qs[r][k]      = qbase[(size_t)r * HW + pb + k];
            else        ks[r - HD][k] = kbase[(size_t)(r - HD) * HW + pb + k];
        }
        __syncthreads();
        #pragma unroll 4
        for (int k = 0; k < GBK; k++) {
            float qv[3], kv[3];
            #pragma unroll
            for (int ii = 0; ii < 3; ii++) qv[ii] = qs[ty * 3 + ii][k];
            #pragma unroll
            for (int jj = 0; jj < 3; jj++) kv[jj] = ks[tx * 3 + jj][k];
            #pragma unroll
            for (int ii = 0; ii < 3; ii++)
                #pragma unroll
                for (int jj = 0; jj < 3; jj++) acc[ii][jj] += qv[ii] * kv[jj];
        }
        __syncthreads();
    }
    float* dst = g_attn + (size_t)bh * HD * HD;
    #pragma unroll
    for (int ii = 0; ii < 3; ii++)
        #pragma unroll
        for (int jj = 0; jj < 3; jj++)
            atomicAdd(&dst[(ty * 3 + ii) * HD + tx * 3 + jj], acc[ii][jj]);
}

// ---------------------------------------------------------------------------
// Softmax per row, fused l2norm scaling + temperature
// ---------------------------------------------------------------------------
__global__ void softmax_kernel(const float* __restrict__ temp)
{
    int bh = blockIdx.x;
    int b = bh >> 3, h = bh & 7;
    int i = threadIdx.x;
    if (i >= HD) return;
    float* row = g_attn + (size_t)bh * HD * HD + i * HD;
    float qi = g_invq[b * C + h * HD + i] * temp[h];
    float vals[HD];
    float mx = -1e30f;
    #pragma unroll
    for (int j = 0; j < HD; j++) {
        float v = row[j] * qi * g_invk[b * C + h * HD + j];
        vals[j] = v;
        mx = fmaxf(mx, v);
    }
    float s = 0.f;
    #pragma unroll
    for (int j = 0; j < HD; j++) { vals[j] = expf(vals[j] - mx); s += vals[j]; }
    float inv = 1.f / s;
    #pragma unroll
    for (int j = 0; j < HD; j++) row[j] = vals[j] * inv;
}

// ---------------------------------------------------------------------------
// wm = W_proj @ blockdiag(attn) -> bf16
// ---------------------------------------------------------------------------
__global__ void wm_kernel(const float* __restrict__ wproj)
{
    int idx = blockIdx.x * 256 + threadIdx.x;
    if (idx >= Bq * C * C) return;
    int cc = idx % C;
    int o  = (idx / C) % C;
    int b  = idx / (C * C);
    int h = cc / HD, ci = cc % HD;
    const float* wrow = wproj + (size_t)o * C + h * HD;
    const float* arow = g_attn + ((size_t)(b * HEADS + h) * HD) * HD + ci;
    float s = 0.f;
    #pragma unroll
    for (int d = 0; d < HD; d++) s += wrow[d] * arow[d * HD];
    g_wmb[idx] = __float2bfloat16(s);
}

// ---------------------------------------------------------------------------
// Launch sequence
// ---------------------------------------------------------------------------
extern "C" void kernel_launch(void* const* d_in, const int* in_sizes, int n_in,
                              void* d_out, int out_size)
{
    const float* x      = (const float*)d_in[0];
    const float* temp   = (const float*)d_in[1];
    const float* ln1w   = (const float*)d_in[2];
    const float* ln1b   = (const float*)d_in[3];
    const float* ln2w   = (const float*)d_in[4];
    const float* ln2b   = (const float*)d_in[5];
    const float* w_qkv  = (const float*)d_in[6];
    const float* w_qkvd = (const float*)d_in[7];
    const float* w_proj = (const float*)d_in[8];
    const float* w_in   = (const float*)d_in[9];
    const float* w_dw   = (const float*)d_in[10];
    const float* w_out  = (const float*)d_in[11];
    float* out = (float*)d_out;

    float *p_t1, *p_t2, *p_xmid;
    __nv_bfloat16 *p_lnb, *p_gate, *p_wqkvb, *p_winb, *p_woutb, *p_wmb;
    cudaGetSymbolAddress((void**)&p_t1,    g_t1);
    cudaGetSymbolAddress((void**)&p_t2,    g_t2);
    cudaGetSymbolAddress((void**)&p_xmid,  g_xmid);
    cudaGetSymbolAddress((void**)&p_lnb,   g_lnb);
    cudaGetSymbolAddress((void**)&p_gate,  g_gate);
    cudaGetSymbolAddress((void**)&p_wqkvb, g_wqkvb);
    cudaGetSymbolAddress((void**)&p_winb,  g_winb);
    cudaGetSymbolAddress((void**)&p_woutb, g_woutb);
    cudaGetSymbolAddress((void**)&p_wmb,   g_wmb);

    const long sC   = (long)C * HW;
    const long sC3  = (long)C3 * HW;
    const long sFF2 = (long)FF2 * HW;
    const long sHID = (long)HIDDEN * HW;

    // 0. weight conversions (bf16, K-padded where needed)
    convw_kernel<<<(C3 * C + 255) / 256, 256>>>(w_qkv, p_wqkvb, C3, C, C);
    convw_kernel<<<(FF2 * C + 255) / 256, 256>>>(w_in, p_winb, FF2, C, C);
    convw_kernel<<<(C * KOUTP + 255) / 256, 256>>>(w_out, p_woutb, C, HIDDEN, KOUTP);

    // 1. ln1(x) -> g_lnb (bf16)
    ln_kernel<<<(Bq * HW + 255) / 256, 256>>>(x, ln1w, ln1b, p_lnb);

    // 2. qkv = W_qkv @ ln -> g_t1 (fp32)
    bf16_gemm_kernel<true><<<dim3(HW / BN, (C3 + BM - 1) / BM, Bq), 256>>>(
        p_wqkvb, p_lnb, p_t1, nullptr, C3, HW, C, C, 0, sC, sC3);

    // 3. zero accumulators
    zero_kernel<<<(Bq * HEADS * HD * HD + 255) / 256, 256>>>();

    // 4. tiled qkv depthwise 3x3 + fused q/k sumsq -> g_t2
    dwconv_qkv_kernel<<<Bq * C3 * 4, 256>>>(p_t1, w_qkvd, p_t2);

    // 5. finalize inverse norms
    invfin_kernel<<<(Bq * 2 * C + 255) / 256, 256>>>();

    // 6. q @ k^T gram matrices
    gram_kernel<<<dim3(Bq * HEADS, GSPLIT), 64>>>();

    // 7. softmax (fused normalization + temperature)
    softmax_kernel<<<Bq * HEADS, 32>>>(temp);

    // 8. wm = W_proj @ blockdiag(attn) -> bf16
    wm_kernel<<<(Bq * C * C + 255) / 256, 256>>>(w_proj);

    // 9. xmid = wm @ v + x   (v fp32 path)
    bf16_gemm_kernel<false><<<dim3(HW / BN, (C + BM - 1) / BM, Bq), 256>>>(
        p_wmb, p_t2 + (size_t)2 * C * HW, p_xmid, x,
        C, HW, C, C, (long)C * C, sC3, sC);

    // 10. ln2(xmid) -> g_lnb (bf16)
    ln_kernel<<<(Bq * HW + 255) / 256, 256>>>(p_xmid, ln2w, ln2b, p_lnb);

    // 11. ffn hidden = W_in @ ln -> g_t1 (fp32)
    bf16_gemm_kernel<true><<<dim3(HW / BN, (FF2 + BM - 1) / BM, Bq), 256>>>(
        p_winb, p_lnb, p_t1, nullptr, FF2, HW, C, C, 0, sC, sFF2);

    // 12. tiled depthwise 3x3 + gelu gate -> g_gate (bf16)
    dwgate_kernel<<<Bq * HIDDEN * 4, 256>>>(p_t1, w_dw, p_gate);

    // 13. out = W_out @ gated + xmid  (K=510 padded to 512)
    bf16_gemm_kernel<true><<<dim3(HW / BN, (C + BM - 1) / BM, Bq), 256>>>(
        p_woutb, p_gate, out, p_xmid, C, HW, KOUTP, HIDDEN, 0, sHID, sC);
}

// round 9
// speedup vs baseline: 4.3936x; 1.0915x over previous
#include <cuda_runtime.h>
#include <cuda_bf16.h>
#include <math.h>

// Problem constants
#define Bq      4
#define C       192
#define C3      576
#define HEADS   8
#define HD      24
#define HIDDEN  510
#define FF2     1020
#define Hh      128
#define Wd      128
#define HW      16384
#define EPS_LN  1e-5f
#define KOUTP   512

// ---------------------------------------------------------------------------
// Static scratch
// ---------------------------------------------------------------------------
__device__ float g_t2  [(size_t)Bq * C3  * HW];   // qkv post-dw (q,k,v) fp32
__device__ float g_xmid[(size_t)Bq * C   * HW];
__device__ float g_attn[Bq * HEADS * HD * HD];
__device__ float g_sq  [Bq * 2 * C];
__device__ float g_invq[Bq * C];
__device__ float g_invk[Bq * C];

__device__ __nv_bfloat16 g_t1b [(size_t)Bq * FF2    * HW];  // qkv pre-dw / ffn pre-dw (bf16)
__device__ __nv_bfloat16 g_lnb [(size_t)Bq * C      * HW];  // LN output (bf16)
__device__ __nv_bfloat16 g_gate[(size_t)Bq * HIDDEN * HW];  // gated FFN (bf16)
__device__ __nv_bfloat16 g_wqkvb[C3 * C];
__device__ __nv_bfloat16 g_winb [FF2 * C];
__device__ __nv_bfloat16 g_woutb[C * KOUTP];
__device__ __nv_bfloat16 g_wmb  [Bq * C * C];

// ---------------------------------------------------------------------------
// Weight fp32 -> bf16 conversion (with K padding)
// ---------------------------------------------------------------------------
__global__ void convw_kernel(const float* __restrict__ src, __nv_bfloat16* __restrict__ dst,
                             int M, int K, int Kpad)
{
    int idx = blockIdx.x * 256 + threadIdx.x;
    if (idx >= M * Kpad) return;
    int m = idx / Kpad, k = idx % Kpad;
    dst[idx] = (k < K) ? __float2bfloat16(src[(size_t)m * K + k]) : __float2bfloat16(0.f);
}

// ---------------------------------------------------------------------------
// Single-read LayerNorm over channel dim -> bf16
// block = 256 threads = 64 pixels x 4 channel-groups (48 ch each); values in regs
// ---------------------------------------------------------------------------
__global__ void __launch_bounds__(256)
ln_kernel(const float* __restrict__ x, const float* __restrict__ w,
          const float* __restrict__ bias, __nv_bfloat16* __restrict__ out)
{
    int blk = blockIdx.x;                 // 0 .. Bq*256-1
    int b   = blk >> 8;
    int p0  = (blk & 255) << 6;           // 64-pixel group
    int px  = threadIdx.x & 63;
    int cg  = threadIdx.x >> 6;           // 0..3

    const float* xp = x + (size_t)b * C * HW + p0 + px;
    float v[48];
    float s = 0.f, s2 = 0.f;
    #pragma unroll
    for (int c = 0; c < 48; c++) {
        float t = xp[(size_t)(cg * 48 + c) * HW];
        v[c] = t; s += t; s2 += t * t;
    }

    __shared__ float ss[4][64], ss2[4][64];
    ss[cg][px] = s; ss2[cg][px] = s2;
    __syncthreads();
    float S  = ss[0][px]  + ss[1][px]  + ss[2][px]  + ss[3][px];
    float S2 = ss2[0][px] + ss2[1][px] + ss2[2][px] + ss2[3][px];
    float mu  = S * (1.f / C);
    float var = S2 * (1.f / C) - mu * mu;
    float r   = rsqrtf(var + EPS_LN);

    __nv_bfloat16* op = out + (size_t)b * C * HW + p0 + px;
    #pragma unroll
    for (int c = 0; c < 48; c++) {
        int ch = cg * 48 + c;
        op[(size_t)ch * HW] = __float2bfloat16((v[c] - mu) * r * __ldg(&w[ch]) + __ldg(&bias[ch]));
    }
}

// ---------------------------------------------------------------------------
// BF16 GEMM with ldmatrix fragment loads
// C[b] (MxN) = W[b] (MxKpad bf16) @ X[b] (KrealxN) (+ Res)
// BM=128 BN=128 BK=16; 8 warps; warp tile 32m x 64n
// A smem [m][k] pitch 24 bf16; B smem [k][n] XOR-swizzled 16B chunks
// ---------------------------------------------------------------------------
#define BM 128
#define BN 128
#define BK 16
#define APITCH 24

__device__ __forceinline__ unsigned pack_bf2(float lo, float hi)
{
    __nv_bfloat162 v = __floats2bfloat162_rn(lo, hi);
    return *(unsigned*)&v;
}

__device__ __forceinline__ void mma_bf16(float c[4], const unsigned a[4], const unsigned* b2)
{
    asm volatile(
        "mma.sync.aligned.m16n8k16.row.col.f32.bf16.bf16.f32 "
        "{%0,%1,%2,%3}, {%4,%5,%6,%7}, {%8,%9}, {%0,%1,%2,%3};"
        : "+f"(c[0]), "+f"(c[1]), "+f"(c[2]), "+f"(c[3])
        : "r"(a[0]), "r"(a[1]), "r"(a[2]), "r"(a[3]), "r"(b2[0]), "r"(b2[1]));
}

__device__ __forceinline__ void ldsm_x4(unsigned r[4], unsigned addr)
{
    asm volatile("ldmatrix.sync.aligned.m8n8.x4.shared.b16 {%0,%1,%2,%3}, [%4];"
                 : "=r"(r[0]), "=r"(r[1]), "=r"(r[2]), "=r"(r[3]) : "r"(addr));
}

__device__ __forceinline__ void ldsm_x4_t(unsigned r[4], unsigned addr)
{
    asm volatile("ldmatrix.sync.aligned.m8n8.x4.trans.shared.b16 {%0,%1,%2,%3}, [%4];"
                 : "=r"(r[0]), "=r"(r[1]), "=r"(r[2]), "=r"(r[3]) : "r"(addr));
}

template<bool XBF16, bool OUTBF16>
__global__ void __launch_bounds__(256, 2)
bf16_gemm_kernel(const __nv_bfloat16* __restrict__ Wt, const void* __restrict__ Xv,
                 void* __restrict__ Om, const float* __restrict__ Res,
                 int M, int N, int Kpad, int Kreal,
                 long wB, long xB, long cB)
{
    const int b = blockIdx.z;
    const __nv_bfloat16* Wb = Wt + (size_t)b * wB;
    const __nv_bfloat16* Xh = XBF16 ? ((const __nv_bfloat16*)Xv + (size_t)b * xB) : nullptr;
    const float*         Xf = XBF16 ? nullptr : ((const float*)Xv + (size_t)b * xB);
    const float* Rb = Res ? (Res + (size_t)b * cB) : nullptr;

    __shared__ __nv_bfloat16 As[BM][APITCH];   // [m][k], pitch 24 (48B)
    __shared__ __nv_bfloat16 Bs[BK][BN];       // [k][n], 16B chunks XOR-swizzled

    const int tid  = threadIdx.x;
    const int lane = tid & 31, warp = tid >> 5;
    const int wm = warp & 3;
    const int wn = warp >> 2;
    const int g  = lane >> 2;
    const int tg = lane & 3;

    const int m0 = blockIdx.y * BM;
    const int n0 = blockIdx.x * BN;

    float acc[2][8][4];
    #pragma unroll
    for (int i = 0; i < 2; i++)
        #pragma unroll
        for (int j = 0; j < 8; j++)
            #pragma unroll
            for (int q = 0; q < 4; q++) acc[i][j][q] = 0.f;

    // loop-invariant ldmatrix addresses
    unsigned aaddr[2], baddr[4];
    {
        int arow = wm * 32 + (lane & 15);
        int koff = (lane >> 4) * 8;
        #pragma unroll
        for (int i = 0; i < 2; i++)
            aaddr[i] = (unsigned)__cvta_generic_to_shared(&As[arow + i * 16][koff]);
        int kk = lane & 15;
        #pragma unroll
        for (int jp = 0; jp < 4; jp++) {
            int cidx = wn * 8 + jp * 2 + (lane >> 4);
            int col  = (cidx ^ (kk & 7)) * 8;
            baddr[jp] = (unsigned)__cvta_generic_to_shared(&Bs[kk][col]);
        }
    }

    // global load indices
    const int ar  = tid >> 1;            // A row 0..127
    const int ah  = (tid & 1) * 8;       // A k-halves
    const int kq  = tid >> 4;            // B k-row 0..15
    const int cq  = tid & 15;            // B 16B chunk 0..15
    const int bcol = (cq ^ (kq & 7)) * 8;

    uint4  aR = make_uint4(0, 0, 0, 0);
    uint4  xR = make_uint4(0, 0, 0, 0);
    float4 fA = make_float4(0.f, 0.f, 0.f, 0.f), fB = fA;

    // prefetch k0 = 0
    {
        if (m0 + ar < M) aR = *(const uint4*)&Wb[(size_t)(m0 + ar) * Kpad + ah];
        if (kq < Kreal) {
            if (XBF16) xR = *(const uint4*)&Xh[(size_t)kq * N + n0 + cq * 8];
            else {
                fA = *(const float4*)&Xf[(size_t)kq * N + n0 + cq * 8];
                fB = *(const float4*)&Xf[(size_t)kq * N + n0 + cq * 8 + 4];
            }
        }
    }

    for (int k0 = 0; k0 < Kpad; k0 += BK) {
        // commit to smem
        *(uint4*)&As[ar][ah] = aR;
        if (XBF16) {
            *(uint4*)&Bs[kq][bcol] = xR;
        } else {
            uint4 p;
            p.x = pack_bf2(fA.x, fA.y);
            p.y = pack_bf2(fA.z, fA.w);
            p.z = pack_bf2(fB.x, fB.y);
            p.w = pack_bf2(fB.z, fB.w);
            *(uint4*)&Bs[kq][bcol] = p;
        }
        __syncthreads();

        // prefetch next
        if (k0 + BK < Kpad) {
            if (m0 + ar < M) aR = *(const uint4*)&Wb[(size_t)(m0 + ar) * Kpad + k0 + BK + ah];
            else             aR = make_uint4(0, 0, 0, 0);
            int kr = k0 + BK + kq;
            if (kr < Kreal) {
                if (XBF16) xR = *(const uint4*)&Xh[(size_t)kr * N + n0 + cq * 8];
                else {
                    fA = *(const float4*)&Xf[(size_t)kr * N + n0 + cq * 8];
                    fB = *(const float4*)&Xf[(size_t)kr * N + n0 + cq * 8 + 4];
                }
            } else {
                xR = make_uint4(0, 0, 0, 0);
                fA = make_float4(0.f, 0.f, 0.f, 0.f);
                fB = fA;
            }
        }

        // fragments via ldmatrix, then 16 MMAs
        {
            unsigned af[2][4], bq4[4][4];
            ldsm_x4(af[0], aaddr[0]);
            ldsm_x4(af[1], aaddr[1]);
            #pragma unroll
            for (int jp = 0; jp < 4; jp++) ldsm_x4_t(bq4[jp], baddr[jp]);
            #pragma unroll
            for (int i = 0; i < 2; i++)
                #pragma unroll
                for (int j = 0; j < 8; j++)
                    mma_bf16(acc[i][j], af[i], &bq4[j >> 1][(j & 1) * 2]);
        }
        __syncthreads();
    }

    // Epilogue
    #pragma unroll
    for (int i = 0; i < 2; i++) {
        int r0 = m0 + wm * 32 + i * 16 + g;
        #pragma unroll
        for (int j = 0; j < 8; j++) {
            int cc = n0 + wn * 64 + j * 8 + tg * 2;
            #pragma unroll
            for (int h = 0; h < 2; h++) {
                int rr = r0 + h * 8;
                if (rr >= M) continue;
                size_t o = (size_t)rr * N + cc;
                float vx = acc[i][j][h * 2], vy = acc[i][j][h * 2 + 1];
                if (Rb) { float2 r = *(const float2*)&Rb[o]; vx += r.x; vy += r.y; }
                if (OUTBF16) {
                    *(unsigned*)&((__nv_bfloat16*)Om)[(size_t)b * cB + o] = pack_bf2(vx, vy);
                } else {
                    *(float2*)&((float*)Om)[(size_t)b * cB + o] = make_float2(vx, vy);
                }
            }
        }
    }
}

// ---------------------------------------------------------------------------
// Tiled depthwise 3x3 (bf16 input), strip = 32 rows; smem halo 34x128 fp32
// ---------------------------------------------------------------------------
#define SROWS 32

__device__ __forceinline__ void load_tile_bf16(float (*tile)[Wd],
                                               const __nv_bfloat16* __restrict__ ip,
                                               int r0, int tid)
{
    #pragma unroll
    for (int i = tid; i < 34 * 32; i += 256) {
        int rr = i >> 5, cg = (i & 31) << 2;
        int gr = r0 + rr;
        float4 v = make_float4(0.f, 0.f, 0.f, 0.f);
        if (gr >= 0 && gr < Hh) {
            uint2 u = *(const uint2*)&ip[gr * Wd + cg];
            __nv_bfloat162 lo = *(__nv_bfloat162*)&u.x;
            __nv_bfloat162 hi = *(__nv_bfloat162*)&u.y;
            v.x = __bfloat162float(lo.x); v.y = __bfloat162float(lo.y);
            v.z = __bfloat162float(hi.x); v.w = __bfloat162float(hi.y);
        }
        *(float4*)&tile[rr][cg] = v;
    }
}

__device__ __forceinline__ void ldrow(const float (*tile)[Wd], int r, int tx,
                                      float& m, float& c, float& p)
{
    c = tile[r][tx];
    m = (tx > 0)      ? tile[r][tx - 1] : 0.f;
    p = (tx < Wd - 1) ? tile[r][tx + 1] : 0.f;
}

// ---------------------------------------------------------------------------
// qkv depthwise conv (bf16 in, fp32 out) + fused q/k sum-of-squares
// ---------------------------------------------------------------------------
__global__ void __launch_bounds__(256)
dwconv_qkv_kernel(const __nv_bfloat16* __restrict__ in, const float* __restrict__ w,
                  float* __restrict__ out)
{
    __shared__ float tile[34][Wd];
    __shared__ float red[256];

    int strip = blockIdx.x & 3;
    int bc    = blockIdx.x >> 2;
    int c = bc % C3;
    int b = bc / C3;
    int tid = threadIdx.x;

    load_tile_bf16(tile, in + ((size_t)bc << 14), strip * SROWS - 1, tid);

    float wreg[9];
    #pragma unroll
    for (int i = 0; i < 9; i++) wreg[i] = __ldg(&w[(size_t)c * 9 + i]);
    __syncthreads();

    int tx   = tid & 127;
    int tseg = tid >> 7;
    int rb   = tseg * 16;

    float t0m, t0c, t0p, t1m, t1c, t1p, t2m, t2c, t2p;
    ldrow(tile, rb,     tx, t0m, t0c, t0p);
    ldrow(tile, rb + 1, tx, t1m, t1c, t1p);

    float* op = out + ((size_t)bc << 14) + (strip * SROWS + rb) * Wd + tx;
    float sq = 0.f;

    #pragma unroll
    for (int rr = 0; rr < 16; rr++) {
        ldrow(tile, rb + rr + 2, tx, t2m, t2c, t2p);
        float s = wreg[0] * t0m + wreg[1] * t0c + wreg[2] * t0p
                + wreg[3] * t1m + wreg[4] * t1c + wreg[5] * t1p
                + wreg[6] * t2m + wreg[7] * t2c + wreg[8] * t2p;
        op[rr * Wd] = s;
        sq += s * s;
        t0m = t1m; t0c = t1c; t0p = t1p;
        t1m = t2m; t1c = t2c; t1p = t2p;
    }

    if (c < 2 * C) {
        red[tid] = sq;
        __syncthreads();
        #pragma unroll
        for (int st = 128; st > 0; st >>= 1) {
            if (tid < st) red[tid] += red[tid + st];
            __syncthreads();
        }
        if (tid == 0) atomicAdd(&g_sq[b * 2 * C + c], red[0]);
    }
}

// ---------------------------------------------------------------------------
// FFN depthwise conv + fused gelu gate (bf16 in/out)
// ---------------------------------------------------------------------------
__global__ void __launch_bounds__(256)
dwgate_kernel(const __nv_bfloat16* __restrict__ in, const float* __restrict__ w,
              __nv_bfloat16* __restrict__ out)
{
    __shared__ float tileA[34][Wd];
    __shared__ float tileB[34][Wd];

    int strip = blockIdx.x & 3;
    int bj    = blockIdx.x >> 2;
    int j = bj % HIDDEN;
    int b = bj / HIDDEN;
    int tid = threadIdx.x;

    int r0 = strip * SROWS - 1;
    load_tile_bf16(tileA, in + (((size_t)b * FF2 + j) << 14), r0, tid);
    load_tile_bf16(tileB, in + (((size_t)b * FF2 + HIDDEN + j) << 14), r0, tid);

    float wa[9], wb[9];
    #pragma unroll
    for (int i = 0; i < 9; i++) {
        wa[i] = __ldg(&w[(size_t)j * 9 + i]);
        wb[i] = __ldg(&w[(size_t)(HIDDEN + j) * 9 + i]);
    }
    __syncthreads();

    int tx   = tid & 127;
    int tseg = tid >> 7;
    int rb   = tseg * 16;

    float a0m, a0c, a0p, a1m, a1c, a1p, a2m, a2c, a2p;
    float b0m, b0c, b0p, b1m, b1c, b1p, b2m, b2c, b2p;
    ldrow(tileA, rb,     tx, a0m, a0c, a0p);
    ldrow(tileA, rb + 1, tx, a1m, a1c, a1p);
    ldrow(tileB, rb,     tx, b0m, b0c, b0p);
    ldrow(tileB, rb + 1, tx, b1m, b1c, b1p);

    __nv_bfloat16* op = out + (((size_t)b * HIDDEN + j) << 14) + (strip * SROWS + rb) * Wd + tx;

    #pragma unroll
    for (int rr = 0; rr < 16; rr++) {
        ldrow(tileA, rb + rr + 2, tx, a2m, a2c, a2p);
        ldrow(tileB, rb + rr + 2, tx, b2m, b2c, b2p);
        float s1 = wa[0] * a0m + wa[1] * a0c + wa[2] * a0p
                 + wa[3] * a1m + wa[4] * a1c + wa[5] * a1p
                 + wa[6] * a2m + wa[7] * a2c + wa[8] * a2p;
        float s2 = wb[0] * b0m + wb[1] * b0c + wb[2] * b0p
                 + wb[3] * b1m + wb[4] * b1c + wb[5] * b1p
                 + wb[6] * b2m + wb[7] * b2c + wb[8] * b2p;
        float gl = 0.5f * s1 * (1.f + erff(s1 * 0.70710678118654752f));
        op[rr * Wd] = __float2bfloat16(gl * s2);
        a0m = a1m; a0c = a1c; a0p = a1p;
        a1m = a2m; a1c = a2c; a1p = a2p;
        b0m = b1m; b0c = b1c; b0p = b1p;
        b1m = b2m; b1c = b2c; b1p = b2p;
    }
}

// ---------------------------------------------------------------------------
// zero accumulators / finalize norms
// ---------------------------------------------------------------------------
__global__ void zero_kernel()
{
    int i = blockIdx.x * 256 + threadIdx.x;
    if (i < Bq * HEADS * HD * HD) g_attn[i] = 0.f;
    if (i < Bq * 2 * C) g_sq[i] = 0.f;
}

__global__ void invfin_kernel()
{
    int i = blockIdx.x * 256 + threadIdx.x;
    if (i >= Bq * 2 * C) return;
    int b = i / (2 * C), c = i % (2 * C);
    float inv = 1.f / fmaxf(sqrtf(g_sq[i]), 1e-12f);
    if (c < C) g_invq[b * C + c] = inv;
    else       g_invk[b * C + c - C] = inv;
}

// ---------------------------------------------------------------------------
// Gram matrices (split-K atomics)
// ---------------------------------------------------------------------------
#define GSPLIT 16
#define GBK    128
__global__ void gram_kernel()
{
    int bh = blockIdx.x;
    int split = blockIdx.y;
    int b = bh >> 3, h = bh & 7;
    const float* qbase = g_t2 + ((size_t)b * C3 + h * HD) * HW;
    const float* kbase = g_t2 + ((size_t)b * C3 + C + h * HD) * HW;

    __shared__ float qs[HD][GBK + 4];
    __shared__ float ks[HD][GBK + 4];

    int tid = threadIdx.x;
    int tx = tid & 7, ty = tid >> 3;
    float acc[3][3] = {{0.f}};

    int p0 = split * (HW / GSPLIT);
    for (int t = 0; t < (HW / GSPLIT) / GBK; t++) {
        int pb = p0 + t * GBK;
        for (int i = tid; i < 2 * HD * GBK; i += 64) {
            int r = i >> 7, k = i & (GBK - 1);
            if (r < HD) qs[r][k]      = qbase[(size_t)r * HW + pb + k];
            else        ks[r - HD][k] = kbase[(size_t)(r - HD) * HW + pb + k];
        }
        __syncthreads();
        #pragma unroll 4
        for (int k = 0; k < GBK; k++) {
            float qv[3], kv[3];
            #pragma unroll
            for (int ii = 0; ii < 3; ii++) qv[ii] = qs[ty * 3 + ii][k];
            #pragma unroll
            for (int jj = 0; jj < 3; jj++) kv[jj] = ks[tx * 3 + jj][k];
            #pragma unroll
            for (int ii = 0; ii < 3; ii++)
                #pragma unroll
                for (int jj = 0; jj < 3; jj++) acc[ii][jj] += qv[ii] * kv[jj];
        }
        __syncthreads();
    }
    float* dst = g_attn + (size_t)bh * HD * HD;
    #pragma unroll
    for (int ii = 0; ii < 3; ii++)
        #pragma unroll
        for (int jj = 0; jj < 3; jj++)
            atomicAdd(&dst[(ty * 3 + ii) * HD + tx * 3 + jj], acc[ii][jj]);
}

// ---------------------------------------------------------------------------
// Softmax per row, fused l2norm scaling + temperature
// ---------------------------------------------------------------------------
__global__ void softmax_kernel(const float* __restrict__ temp)
{
    int bh = blockIdx.x;
    int b = bh >> 3, h = bh & 7;
    int i = threadIdx.x;
    if (i >= HD) return;
    float* row = g_attn + (size_t)bh * HD * HD + i * HD;
    float qi = g_invq[b * C + h * HD + i] * temp[h];
    float vals[HD];
    float mx = -1e30f;
    #pragma unroll
    for (int j = 0; j < HD; j++) {
        float v = row[j] * qi * g_invk[b * C + h * HD + j];
        vals[j] = v;
        mx = fmaxf(mx, v);
    }
    float s = 0.f;
    #pragma unroll
    for (int j = 0; j < HD; j++) { vals[j] = expf(vals[j] - mx); s += vals[j]; }
    float inv = 1.f / s;
    #pragma unroll
    for (int j = 0; j < HD; j++) row[j] = vals[j] * inv;
}

// ---------------------------------------------------------------------------
// wm = W_proj @ blockdiag(attn) -> bf16
// ---------------------------------------------------------------------------
__global__ void wm_kernel(const float* __restrict__ wproj)
{
    int idx = blockIdx.x * 256 + threadIdx.x;
    if (idx >= Bq * C * C) return;
    int cc = idx % C;
    int o  = (idx / C) % C;
    int b  = idx / (C * C);
    int h = cc / HD, ci = cc % HD;
    const float* wrow = wproj + (size_t)o * C + h * HD;
    const float* arow = g_attn + ((size_t)(b * HEADS + h) * HD) * HD + ci;
    float s = 0.f;
    #pragma unroll
    for (int d = 0; d < HD; d++) s += wrow[d] * arow[d * HD];
    g_wmb[idx] = __float2bfloat16(s);
}

// ---------------------------------------------------------------------------
// Launch sequence
// ---------------------------------------------------------------------------
extern "C" void kernel_launch(void* const* d_in, const int* in_sizes, int n_in,
                              void* d_out, int out_size)
{
    const float* x      = (const float*)d_in[0];
    const float* temp   = (const float*)d_in[1];
    const float* ln1w   = (const float*)d_in[2];
    const float* ln1b   = (const float*)d_in[3];
    const float* ln2w   = (const float*)d_in[4];
    const float* ln2b   = (const float*)d_in[5];
    const float* w_qkv  = (const float*)d_in[6];
    const float* w_qkvd = (const float*)d_in[7];
    const float* w_proj = (const float*)d_in[8];
    const float* w_in   = (const float*)d_in[9];
    const float* w_dw   = (const float*)d_in[10];
    const float* w_out  = (const float*)d_in[11];
    float* out = (float*)d_out;

    float *p_t2, *p_xmid;
    __nv_bfloat16 *p_t1b, *p_lnb, *p_gate, *p_wqkvb, *p_winb, *p_woutb, *p_wmb;
    cudaGetSymbolAddress((void**)&p_t2,    g_t2);
    cudaGetSymbolAddress((void**)&p_xmid,  g_xmid);
    cudaGetSymbolAddress((void**)&p_t1b,   g_t1b);
    cudaGetSymbolAddress((void**)&p_lnb,   g_lnb);
    cudaGetSymbolAddress((void**)&p_gate,  g_gate);
    cudaGetSymbolAddress((void**)&p_wqkvb, g_wqkvb);
    cudaGetSymbolAddress((void**)&p_winb,  g_winb);
    cudaGetSymbolAddress((void**)&p_woutb, g_woutb);
    cudaGetSymbolAddress((void**)&p_wmb,   g_wmb);

    const long sC   = (long)C * HW;
    const long sC3  = (long)C3 * HW;
    const long sFF2 = (long)FF2 * HW;
    const long sHID = (long)HIDDEN * HW;

    // 0. weight conversions
    convw_kernel<<<(C3 * C + 255) / 256, 256>>>(w_qkv, p_wqkvb, C3, C, C);
    convw_kernel<<<(FF2 * C + 255) / 256, 256>>>(w_in, p_winb, FF2, C, C);
    convw_kernel<<<(C * KOUTP + 255) / 256, 256>>>(w_out, p_woutb, C, HIDDEN, KOUTP);

    // 1. ln1(x) -> g_lnb
    ln_kernel<<<Bq * 256, 256>>>(x, ln1w, ln1b, p_lnb);

    // 2. qkv = W_qkv @ ln -> g_t1b (bf16)
    bf16_gemm_kernel<true, true><<<dim3(HW / BN, (C3 + BM - 1) / BM, Bq), 256>>>(
        p_wqkvb, p_lnb, p_t1b, nullptr, C3, HW, C, C, 0, sC, sC3);

    // 3. zero accumulators
    zero_kernel<<<(Bq * HEADS * HD * HD + 255) / 256, 256>>>();

    // 4. tiled qkv depthwise 3x3 + fused q/k sumsq -> g_t2 (fp32)
    dwconv_qkv_kernel<<<Bq * C3 * 4, 256>>>(p_t1b, w_qkvd, p_t2);

    // 5. finalize inverse norms
    invfin_kernel<<<(Bq * 2 * C + 255) / 256, 256>>>();

    // 6. q @ k^T gram matrices
    gram_kernel<<<dim3(Bq * HEADS, GSPLIT), 64>>>();

    // 7. softmax (fused normalization + temperature)
    softmax_kernel<<<Bq * HEADS, 32>>>(temp);

    // 8. wm = W_proj @ blockdiag(attn) -> bf16
    wm_kernel<<<(Bq * C * C + 255) / 256, 256>>>(w_proj);

    // 9. xmid = wm @ v + x   (fp32 out + residual)
    bf16_gemm_kernel<false, false><<<dim3(HW / BN, (C + BM - 1) / BM, Bq), 256>>>(
        p_wmb, p_t2 + (size_t)2 * C * HW, p_xmid, x,
        C, HW, C, C, (long)C * C, sC3, sC);

    // 10. ln2(xmid) -> g_lnb
    ln_kernel<<<Bq * 256, 256>>>(p_xmid, ln2w, ln2b, p_lnb);

    // 11. ffn hidden = W_in @ ln -> g_t1b (bf16)
    bf16_gemm_kernel<true, true><<<dim3(HW / BN, (FF2 + BM - 1) / BM, Bq), 256>>>(
        p_winb, p_lnb, p_t1b, nullptr, FF2, HW, C, C, 0, sC, sFF2);

    // 12. tiled depthwise 3x3 + gelu gate -> g_gate (bf16)
    dwgate_kernel<<<Bq * HIDDEN * 4, 256>>>(p_t1b, w_dw, p_gate);

    // 13. out = W_out @ gated + xmid  (K=510 padded to 512, fp32 out + residual)
    bf16_gemm_kernel<true, false><<<dim3(HW / BN, (C + BM - 1) / BM, Bq), 256>>>(
        p_woutb, p_gate, out, p_xmid, C, HW, KOUTP, HIDDEN, 0, sHID, sC);
}